// round 6
// baseline (speedup 1.0000x reference)
#include <cuda_runtime.h>
#include <math.h>
#include <stdint.h>

// Problem constants
#define TKN 2048          // B*N tokens
#define DM 1024           // model dim
#define NE 8              // experts
#define FFD 4096          // ffn dim
#define NH 16             // heads
#define HD 64             // head dim
#define PADROWS 3072      // token rows padded to 128 per expert segment
#define MAXTILES 24       // PADROWS/128

// ---------------- scratch (device globals; no allocation allowed) ----------------
__device__ float g_qkv[TKN * 3 * DM];
__device__ float g_ctx[TKN * DM];
__device__ float g_x[TKN * DM];
__device__ float g_tmp[TKN * DM];
__device__ float g_h[TKN * FFD];
__device__ int   g_idx0[TKN];
__device__ int   g_idx1[TKN];
__device__ float g_gw0[TKN];
__device__ float g_gw1[TKN];
__device__ int   g_perm0[PADROWS];
__device__ int   g_perm1[PADROWS];
__device__ int   g_te0[MAXTILES];
__device__ int   g_te1[MAXTILES];

__device__ __forceinline__ uint32_t f2tf32(float x) {
    uint32_t r;
    asm("cvt.rna.tf32.f32 %0, %1;" : "=r"(r) : "f"(x));
    return r;
}
__device__ __forceinline__ void mma_tf32(float& c0, float& c1, float& c2, float& c3,
                                         uint32_t a0, uint32_t a1, uint32_t a2, uint32_t a3,
                                         uint32_t b0, uint32_t b1) {
    asm volatile(
        "mma.sync.aligned.m16n8k8.row.col.f32.tf32.tf32.f32 "
        "{%0,%1,%2,%3}, {%4,%5,%6,%7}, {%8,%9}, {%0,%1,%2,%3};"
        : "+f"(c0), "+f"(c1), "+f"(c2), "+f"(c3)
        : "r"(a0), "r"(a1), "r"(a2), "r"(a3), "r"(b0), "r"(b1));
}

// ---------------- gate: logits = x @ Wg [D,E], softmax, top-1 ----------------
__global__ void gate_kernel(const float* __restrict__ x, const float* __restrict__ Wg,
                            int* __restrict__ idx, float* __restrict__ gw) {
    int t = blockIdx.x;
    int warp = threadIdx.x >> 5, lane = threadIdx.x & 31;
    const float* xr = x + (size_t)t * DM;
    float s = 0.f;
    #pragma unroll 4
    for (int d = lane; d < DM; d += 32) s += xr[d] * Wg[d * NE + warp];
    #pragma unroll
    for (int o = 16; o; o >>= 1) s += __shfl_xor_sync(0xffffffffu, s, o);
    __shared__ float logits[NE];
    if (lane == 0) logits[warp] = s;
    __syncthreads();
    if (threadIdx.x == 0) {
        float best = logits[0]; int bi = 0;
        #pragma unroll
        for (int e = 1; e < NE; e++) if (logits[e] > best) { best = logits[e]; bi = e; }
        float sum = 0.f;
        #pragma unroll
        for (int e = 0; e < NE; e++) sum += expf(logits[e] - best);
        idx[t] = bi;
        gw[t] = 1.f / sum;
    }
}

// ---------------- scatter: group tokens by expert into 128-aligned segments ----------------
__global__ void scatter_kernel(const int* __restrict__ idx, int* __restrict__ perm,
                               int* __restrict__ tile_expert) {
    __shared__ int cnt[NE];
    __shared__ int cur[NE];
    int tid = threadIdx.x;
    if (tid < NE) cnt[tid] = 0;
    for (int i = tid; i < PADROWS; i += blockDim.x) perm[i] = -1;
    __syncthreads();
    for (int t = tid; t < TKN; t += blockDim.x) atomicAdd(&cnt[idx[t]], 1);
    __syncthreads();
    if (tid == 0) {
        int c = 0;
        for (int e = 0; e < NE; e++) {
            cur[e] = c;
            int tiles = (cnt[e] + 127) >> 7;
            for (int i = 0; i < tiles; i++) tile_expert[(c >> 7) + i] = e;
            c += tiles << 7;
        }
        for (int i = c >> 7; i < MAXTILES; i++) tile_expert[i] = -1;
    }
    __syncthreads();
    for (int t = tid; t < TKN; t += blockDim.x) {
        int p = atomicAdd(&cur[idx[t]], 1);
        perm[p] = t;
    }
}

// ============ tf32 mma.sync MoE GEMM: Out[tok] = ep(gw*(In[tok]@W[e] + b[e])) ============
// 128x128 CTA tile, BK=16, 8 warps (4M x 2N), warp tile 32x64, m16n8k8 tf32.
// smem k-major [16][136] for both A and B: fragment LDS conflict-free.
#define KSTRIDE 136
#define STGW (16 * KSTRIDE)   // words per stage = 2176

__global__ void __launch_bounds__(256, 2)
moe_gemm_mma(const float* __restrict__ In, const float* __restrict__ W,
             const float* __restrict__ bias, const float* __restrict__ gw,
             const int* __restrict__ perm, const int* __restrict__ tile_expert,
             float* __restrict__ Out, int K, int Nout, int gelu_flag) {
    int e = tile_expert[blockIdx.y];
    if (e < 0) return;
    __shared__ uint32_t SA[2][STGW];
    __shared__ uint32_t SB[2][STGW];

    int tid = threadIdx.x, wid = tid >> 5, lane = tid & 31;
    int g = lane >> 2, tg = lane & 3;
    int warp_m = wid & 3, warp_n = wid >> 2;
    int row0 = blockIdx.y << 7, col0 = blockIdx.x << 7;

    // ---- global load mappings ----
    // A: thread handles row mS (0..127), k-half kqS (0 or 8) of each 16-chunk
    int mS = tid & 127;
    int kqS = (tid >> 7) << 3;
    int tokA = perm[row0 + mS];
    const float* aptr = (tokA >= 0) ? (In + (size_t)tokA * K + kqS) : In;
    // B: thread handles k row kBs (0..15), 8 cols at nBs
    int kBs = tid >> 4;
    int nBs = (tid & 15) << 3;
    const float* bptr = W + ((size_t)e * K + kBs) * Nout + col0 + nBs;

    float acc[2][8][4];
    #pragma unroll
    for (int mi = 0; mi < 2; mi++)
        #pragma unroll
        for (int ni = 0; ni < 8; ni++)
            #pragma unroll
            for (int q = 0; q < 4; q++) acc[mi][ni][q] = 0.f;

    int nchunk = K >> 4;

    // ---- prologue: chunk 0 into buffer 0 ----
    {
        float4 av0 = make_float4(0.f,0.f,0.f,0.f), av1 = av0;
        if (tokA >= 0) { av0 = *(const float4*)(aptr); av1 = *(const float4*)(aptr + 4); }
        float4 bv0 = *(const float4*)(bptr);
        float4 bv1 = *(const float4*)(bptr + 4);
        SA[0][(kqS + 0) * KSTRIDE + mS] = f2tf32(av0.x);
        SA[0][(kqS + 1) * KSTRIDE + mS] = f2tf32(av0.y);
        SA[0][(kqS + 2) * KSTRIDE + mS] = f2tf32(av0.z);
        SA[0][(kqS + 3) * KSTRIDE + mS] = f2tf32(av0.w);
        SA[0][(kqS + 4) * KSTRIDE + mS] = f2tf32(av1.x);
        SA[0][(kqS + 5) * KSTRIDE + mS] = f2tf32(av1.y);
        SA[0][(kqS + 6) * KSTRIDE + mS] = f2tf32(av1.z);
        SA[0][(kqS + 7) * KSTRIDE + mS] = f2tf32(av1.w);
        uint32_t* bdst = &SB[0][kBs * KSTRIDE + nBs];
        bdst[0] = f2tf32(bv0.x); bdst[1] = f2tf32(bv0.y);
        bdst[2] = f2tf32(bv0.z); bdst[3] = f2tf32(bv0.w);
        bdst[4] = f2tf32(bv1.x); bdst[5] = f2tf32(bv1.y);
        bdst[6] = f2tf32(bv1.z); bdst[7] = f2tf32(bv1.w);
    }
    __syncthreads();

    int am0 = warp_m * 32 + g;
    int bn0 = warp_n * 64 + g;

    for (int c = 0; c < nchunk; c++) {
        int buf = c & 1;
        bool has_next = (c + 1) < nchunk;
        float4 av0, av1, bv0, bv1;
        if (has_next) {
            int k0 = (c + 1) << 4;
            if (tokA >= 0) {
                av0 = *(const float4*)(aptr + k0);
                av1 = *(const float4*)(aptr + k0 + 4);
            } else { av0 = make_float4(0.f,0.f,0.f,0.f); av1 = av0; }
            const float* bp = bptr + (size_t)k0 * Nout;
            bv0 = *(const float4*)(bp);
            bv1 = *(const float4*)(bp + 4);
        }

        // ---- compute chunk c ----
        const uint32_t* Ab = SA[buf];
        const uint32_t* Bb = SB[buf];
        #pragma unroll
        for (int ks = 0; ks < 2; ks++) {
            int kb = ks << 3;
            uint32_t a[2][4];
            #pragma unroll
            for (int mi = 0; mi < 2; mi++) {
                int m = am0 + mi * 16;
                a[mi][0] = Ab[(kb + tg) * KSTRIDE + m];
                a[mi][1] = Ab[(kb + tg) * KSTRIDE + m + 8];
                a[mi][2] = Ab[(kb + tg + 4) * KSTRIDE + m];
                a[mi][3] = Ab[(kb + tg + 4) * KSTRIDE + m + 8];
            }
            #pragma unroll
            for (int ni = 0; ni < 8; ni++) {
                int n = bn0 + ni * 8;
                uint32_t b0 = Bb[(kb + tg) * KSTRIDE + n];
                uint32_t b1 = Bb[(kb + tg + 4) * KSTRIDE + n];
                mma_tf32(acc[0][ni][0], acc[0][ni][1], acc[0][ni][2], acc[0][ni][3],
                         a[0][0], a[0][1], a[0][2], a[0][3], b0, b1);
                mma_tf32(acc[1][ni][0], acc[1][ni][1], acc[1][ni][2], acc[1][ni][3],
                         a[1][0], a[1][1], a[1][2], a[1][3], b0, b1);
            }
        }

        if (has_next) {
            int nb = buf ^ 1;
            SA[nb][(kqS + 0) * KSTRIDE + mS] = f2tf32(av0.x);
            SA[nb][(kqS + 1) * KSTRIDE + mS] = f2tf32(av0.y);
            SA[nb][(kqS + 2) * KSTRIDE + mS] = f2tf32(av0.z);
            SA[nb][(kqS + 3) * KSTRIDE + mS] = f2tf32(av0.w);
            SA[nb][(kqS + 4) * KSTRIDE + mS] = f2tf32(av1.x);
            SA[nb][(kqS + 5) * KSTRIDE + mS] = f2tf32(av1.y);
            SA[nb][(kqS + 6) * KSTRIDE + mS] = f2tf32(av1.z);
            SA[nb][(kqS + 7) * KSTRIDE + mS] = f2tf32(av1.w);
            uint32_t* bdst = &SB[nb][kBs * KSTRIDE + nBs];
            bdst[0] = f2tf32(bv0.x); bdst[1] = f2tf32(bv0.y);
            bdst[2] = f2tf32(bv0.z); bdst[3] = f2tf32(bv0.w);
            bdst[4] = f2tf32(bv1.x); bdst[5] = f2tf32(bv1.y);
            bdst[6] = f2tf32(bv1.z); bdst[7] = f2tf32(bv1.w);
            __syncthreads();
        }
    }

    // ---- epilogue: rows mbase + {0,8,16,24}, cols warp_n*64 + ni*8 + 2*tg ----
    int tok[4]; float gwv[4];
    #pragma unroll
    for (int q = 0; q < 4; q++) {
        int r = row0 + warp_m * 32 + g + q * 8;
        tok[q] = perm[r];
        gwv[q] = (tok[q] >= 0) ? gw[tok[q]] : 0.f;
    }
    #pragma unroll
    for (int ni = 0; ni < 8; ni++) {
        int col = col0 + warp_n * 64 + ni * 8 + 2 * tg;
        float2 bs2 = *(const float2*)&bias[(size_t)e * Nout + col];
        #pragma unroll
        for (int mi = 0; mi < 2; mi++) {
            #pragma unroll
            for (int half = 0; half < 2; half++) {
                int q = mi * 2 + half;
                if (tok[q] < 0) continue;
                float v0 = (acc[mi][ni][half * 2 + 0] + bs2.x) * gwv[q];
                float v1 = (acc[mi][ni][half * 2 + 1] + bs2.y) * gwv[q];
                if (gelu_flag) {
                    float c0 = v0 + 0.044715f * v0 * v0 * v0;
                    v0 = 0.5f * v0 * (1.f + tanhf(0.7978845608028654f * c0));
                    float c1 = v1 + 0.044715f * v1 * v1 * v1;
                    v1 = 0.5f * v1 * (1.f + tanhf(0.7978845608028654f * c1));
                }
                *(float2*)&Out[(size_t)tok[q] * Nout + col] = make_float2(v0, v1);
            }
        }
    }
}

// ---------------- flash attention: BQ=64, BK=64, DH=64, 256 threads ----------------
#define ATT_SMEM_FLOATS (64 * 64 + 64 * 65 + 64 * 64 + 64 * 16)
__global__ void __launch_bounds__(256)
attn_kernel(const float* __restrict__ qkv, const unsigned char* __restrict__ mask,
            float* __restrict__ ctx) {
    extern __shared__ float sm[];
    float* Qs  = sm;
    float* KPs = Qs + 64 * 64;
    float* Vs  = KPs + 64 * 65;
    float* red = Vs + 64 * 64;

    int bh = blockIdx.y;
    int b = bh >> 4, h = bh & 15;
    int n0 = blockIdx.x << 6;
    int tid = threadIdx.x, tx = tid & 15, ty = tid >> 4;
    int r0 = ty << 2, c0d = tx << 2;

    {
        int r = tid >> 2, d0 = (tid & 3) << 4;
        const float* qp = qkv + (size_t)(b * 1024 + n0 + r) * 3072 + h * 64 + d0;
        #pragma unroll
        for (int i = 0; i < 16; i += 4) {
            float4 v = *(const float4*)(qp + i);
            Qs[r * 64 + d0 + i + 0] = v.x; Qs[r * 64 + d0 + i + 1] = v.y;
            Qs[r * 64 + d0 + i + 2] = v.z; Qs[r * 64 + d0 + i + 3] = v.w;
        }
    }
    __syncthreads();

    float o[4][4];
    float m[4], l[4];
    #pragma unroll
    for (int i = 0; i < 4; i++) {
        m[i] = -1e30f; l[i] = 0.f;
        #pragma unroll
        for (int j = 0; j < 4; j++) o[i][j] = 0.f;
    }

    for (int kt = 0; kt < 16; kt++) {
        {
            int c = tid >> 2, d0 = (tid & 3) << 4;
            const float* base = qkv + (size_t)(b * 1024 + kt * 64 + c) * 3072 + h * 64 + d0;
            #pragma unroll
            for (int i = 0; i < 16; i += 4) {
                float4 kv = *(const float4*)(base + 1024 + i);
                float4 vv = *(const float4*)(base + 2048 + i);
                KPs[c * 65 + d0 + i + 0] = kv.x; KPs[c * 65 + d0 + i + 1] = kv.y;
                KPs[c * 65 + d0 + i + 2] = kv.z; KPs[c * 65 + d0 + i + 3] = kv.w;
                Vs[c * 64 + d0 + i + 0] = vv.x; Vs[c * 64 + d0 + i + 1] = vv.y;
                Vs[c * 64 + d0 + i + 2] = vv.z; Vs[c * 64 + d0 + i + 3] = vv.w;
            }
        }
        __syncthreads();

        float s[4][4];
        #pragma unroll
        for (int i = 0; i < 4; i++)
            #pragma unroll
            for (int j = 0; j < 4; j++) s[i][j] = 0.f;
        for (int d = 0; d < 64; d++) {
            float qf[4], kf[4];
            #pragma unroll
            for (int i = 0; i < 4; i++) qf[i] = Qs[(r0 + i) * 64 + d];
            #pragma unroll
            for (int j = 0; j < 4; j++) kf[j] = KPs[(c0d + j) * 65 + d];
            #pragma unroll
            for (int i = 0; i < 4; i++)
                #pragma unroll
                for (int j = 0; j < 4; j++) s[i][j] += qf[i] * kf[j];
        }
        float mv[4];
        #pragma unroll
        for (int j = 0; j < 4; j++)
            mv[j] = mask[b * 1024 + kt * 64 + c0d + j] ? -10000.f : 0.f;
        #pragma unroll
        for (int i = 0; i < 4; i++)
            #pragma unroll
            for (int j = 0; j < 4; j++) s[i][j] = s[i][j] * 0.125f + mv[j];

        #pragma unroll
        for (int i = 0; i < 4; i++) {
            float rm = fmaxf(fmaxf(s[i][0], s[i][1]), fmaxf(s[i][2], s[i][3]));
            red[(r0 + i) * 16 + tx] = rm;
        }
        __syncthreads();
        float mnew[4], scale[4];
        #pragma unroll
        for (int i = 0; i < 4; i++) {
            float mx = m[i];
            #pragma unroll
            for (int q = 0; q < 16; q++) mx = fmaxf(mx, red[(r0 + i) * 16 + q]);
            mnew[i] = mx;
        }
        __syncthreads();

        float rs[4];
        #pragma unroll
        for (int i = 0; i < 4; i++) {
            scale[i] = expf(m[i] - mnew[i]);
            float ss = 0.f;
            #pragma unroll
            for (int j = 0; j < 4; j++) { s[i][j] = expf(s[i][j] - mnew[i]); ss += s[i][j]; }
            rs[i] = ss; m[i] = mnew[i];
        }
        #pragma unroll
        for (int i = 0; i < 4; i++) red[(r0 + i) * 16 + tx] = rs[i];
        #pragma unroll
        for (int i = 0; i < 4; i++)
            #pragma unroll
            for (int j = 0; j < 4; j++) KPs[(r0 + i) * 65 + c0d + j] = s[i][j];
        __syncthreads();

        #pragma unroll
        for (int i = 0; i < 4; i++) {
            float ss = 0.f;
            #pragma unroll
            for (int q = 0; q < 16; q++) ss += red[(r0 + i) * 16 + q];
            l[i] = l[i] * scale[i] + ss;
            #pragma unroll
            for (int j = 0; j < 4; j++) o[i][j] *= scale[i];
        }
        for (int c = 0; c < 64; c++) {
            float pf[4], vf[4];
            #pragma unroll
            for (int i = 0; i < 4; i++) pf[i] = KPs[(r0 + i) * 65 + c];
            #pragma unroll
            for (int j = 0; j < 4; j++) vf[j] = Vs[c * 64 + c0d + j];
            #pragma unroll
            for (int i = 0; i < 4; i++)
                #pragma unroll
                for (int j = 0; j < 4; j++) o[i][j] += pf[i] * vf[j];
        }
        __syncthreads();
    }

    #pragma unroll
    for (int i = 0; i < 4; i++) {
        int t = b * 1024 + n0 + r0 + i;
        float inv = 1.f / l[i];
        float4 v = make_float4(o[i][0] * inv, o[i][1] * inv, o[i][2] * inv, o[i][3] * inv);
        *(float4*)&ctx[(size_t)t * 1024 + h * 64 + c0d] = v;
    }
}

// ---------------- residual + layernorm ----------------
__global__ void __launch_bounds__(256)
ln_kernel(const float* __restrict__ a, const float* __restrict__ b,
          const float* __restrict__ s, const float* __restrict__ bias,
          float* __restrict__ out) {
    int t = blockIdx.x;
    int base = threadIdx.x << 2;
    const float* ar = a + (size_t)t * DM;
    const float* br = b + (size_t)t * DM;
    float4 av = *(const float4*)(ar + base);
    float4 bv = *(const float4*)(br + base);
    float v[4] = {av.x + bv.x, av.y + bv.y, av.z + bv.z, av.w + bv.w};
    float s1 = v[0] + v[1] + v[2] + v[3];
    float s2 = v[0] * v[0] + v[1] * v[1] + v[2] * v[2] + v[3] * v[3];
    #pragma unroll
    for (int o = 16; o; o >>= 1) {
        s1 += __shfl_xor_sync(0xffffffffu, s1, o);
        s2 += __shfl_xor_sync(0xffffffffu, s2, o);
    }
    __shared__ float w1[8], w2[8];
    __shared__ float sh_mean, sh_inv;
    int warp = threadIdx.x >> 5, lane = threadIdx.x & 31;
    if (lane == 0) { w1[warp] = s1; w2[warp] = s2; }
    __syncthreads();
    if (threadIdx.x == 0) {
        float A = 0.f, B = 0.f;
        #pragma unroll
        for (int i = 0; i < 8; i++) { A += w1[i]; B += w2[i]; }
        float mean = A * (1.f / DM);
        float var = B * (1.f / DM) - mean * mean;
        sh_mean = mean;
        sh_inv = rsqrtf(var + 1e-5f);
    }
    __syncthreads();
    float mean = sh_mean, inv = sh_inv;
    float4 sv = *(const float4*)(s + base);
    float4 biv = *(const float4*)(bias + base);
    float4 ov;
    ov.x = (v[0] - mean) * inv * sv.x + biv.x;
    ov.y = (v[1] - mean) * inv * sv.y + biv.y;
    ov.z = (v[2] - mean) * inv * sv.z + biv.z;
    ov.w = (v[3] - mean) * inv * sv.w + biv.w;
    *(float4*)(out + (size_t)t * DM + base) = ov;
}

// ---------------- launch ----------------
extern "C" void kernel_launch(void* const* d_in, const int* in_sizes, int n_in,
                              void* d_out, int out_size) {
    const float* src     = (const float*)d_in[0];
    const unsigned char* mask = (const unsigned char*)d_in[1];
    const float* Wg_attn = (const float*)d_in[2];
    const float* Wqkv    = (const float*)d_in[3];
    const float* bqkv    = (const float*)d_in[4];
    const float* Wo      = (const float*)d_in[5];
    const float* bo      = (const float*)d_in[6];
    const float* Wg_ffn  = (const float*)d_in[7];
    const float* W1      = (const float*)d_in[8];
    const float* b1      = (const float*)d_in[9];
    const float* W2      = (const float*)d_in[10];
    const float* b2      = (const float*)d_in[11];
    const float* ln1_s   = (const float*)d_in[12];
    const float* ln1_b   = (const float*)d_in[13];
    const float* ln2_s   = (const float*)d_in[14];
    const float* ln2_b   = (const float*)d_in[15];
    float* out = (float*)d_out;

    float *qkv, *ctx, *x, *tmp, *hbuf, *gw0, *gw1;
    int *idx0, *idx1, *perm0, *perm1, *te0, *te1;
    cudaGetSymbolAddress((void**)&qkv,  g_qkv);
    cudaGetSymbolAddress((void**)&ctx,  g_ctx);
    cudaGetSymbolAddress((void**)&x,    g_x);
    cudaGetSymbolAddress((void**)&tmp,  g_tmp);
    cudaGetSymbolAddress((void**)&hbuf, g_h);
    cudaGetSymbolAddress((void**)&gw0,  g_gw0);
    cudaGetSymbolAddress((void**)&gw1,  g_gw1);
    cudaGetSymbolAddress((void**)&idx0, g_idx0);
    cudaGetSymbolAddress((void**)&idx1, g_idx1);
    cudaGetSymbolAddress((void**)&perm0, g_perm0);
    cudaGetSymbolAddress((void**)&perm1, g_perm1);
    cudaGetSymbolAddress((void**)&te0,  g_te0);
    cudaGetSymbolAddress((void**)&te1,  g_te1);

    int att_smem = ATT_SMEM_FLOATS * (int)sizeof(float);
    cudaFuncSetAttribute(attn_kernel, cudaFuncAttributeMaxDynamicSharedMemorySize, att_smem);

    // 1. attention gate + grouping
    gate_kernel<<<TKN, 256>>>(src, Wg_attn, idx0, gw0);
    scatter_kernel<<<1, 256>>>(idx0, perm0, te0);
    // 2. QKV projection (tf32 mma)
    moe_gemm_mma<<<dim3(3 * DM / 128, MAXTILES), 256>>>(
        src, Wqkv, bqkv, gw0, perm0, te0, qkv, DM, 3 * DM, 0);
    // 3. attention
    attn_kernel<<<dim3(1024 / 64, 2 * NH), 256, att_smem>>>(qkv, mask, ctx);
    // 4. output projection
    moe_gemm_mma<<<dim3(DM / 128, MAXTILES), 256>>>(
        ctx, Wo, bo, gw0, perm0, te0, tmp, DM, DM, 0);
    // 5. x = LN1(src + attn_out)
    ln_kernel<<<TKN, 256>>>(src, tmp, ln1_s, ln1_b, x);
    // 6. ffn gate + grouping
    gate_kernel<<<TKN, 256>>>(x, Wg_ffn, idx1, gw1);
    scatter_kernel<<<1, 256>>>(idx1, perm1, te1);
    // 7. h = gelu(gated W1)
    moe_gemm_mma<<<dim3(FFD / 128, MAXTILES), 256>>>(
        x, W1, b1, gw1, perm1, te1, hbuf, DM, FFD, 1);
    // 8. ffn = gated W2
    moe_gemm_mma<<<dim3(DM / 128, MAXTILES), 256>>>(
        hbuf, W2, b2, gw1, perm1, te1, tmp, FFD, DM, 0);
    // 9. out = LN2(x + ffn)
    ln_kernel<<<TKN, 256>>>(x, tmp, ln2_s, ln2_b, out);
}

// round 7
// speedup vs baseline: 1.1444x; 1.1444x over previous
#include <cuda_runtime.h>
#include <math.h>
#include <stdint.h>

// Problem constants
#define TKN 2048          // B*N tokens
#define DM 1024           // model dim
#define NE 8              // experts
#define FFD 4096          // ffn dim
#define NH 16             // heads
#define HD 64             // head dim
#define PADROWS 3072      // token rows padded to 128 per expert segment
#define MAXTILES 24       // PADROWS/128

// ---------------- scratch (device globals; no allocation allowed) ----------------
__device__ float g_qkv[TKN * 3 * DM];
__device__ float g_ctx[TKN * DM];
__device__ float g_x[TKN * DM];
__device__ float g_tmp[TKN * DM];
__device__ float g_h[TKN * FFD];
__device__ int   g_idx0[TKN];
__device__ int   g_idx1[TKN];
__device__ float g_gw0[TKN];
__device__ float g_gw1[TKN];
__device__ int   g_perm0[PADROWS];
__device__ int   g_perm1[PADROWS];
__device__ int   g_te0[MAXTILES];
__device__ int   g_te1[MAXTILES];

__device__ __forceinline__ uint32_t f2tf32(float x) {
    uint32_t r;
    asm("cvt.rna.tf32.f32 %0, %1;" : "=r"(r) : "f"(x));
    return r;
}
__device__ __forceinline__ void mma_tf32(float& c0, float& c1, float& c2, float& c3,
                                         uint32_t a0, uint32_t a1, uint32_t a2, uint32_t a3,
                                         uint32_t b0, uint32_t b1) {
    asm volatile(
        "mma.sync.aligned.m16n8k8.row.col.f32.tf32.tf32.f32 "
        "{%0,%1,%2,%3}, {%4,%5,%6,%7}, {%8,%9}, {%0,%1,%2,%3};"
        : "+f"(c0), "+f"(c1), "+f"(c2), "+f"(c3)
        : "r"(a0), "r"(a1), "r"(a2), "r"(a3), "r"(b0), "r"(b1));
}

// ---------------- gate: logits = x @ Wg [D,E], softmax, top-1 ----------------
__global__ void gate_kernel(const float* __restrict__ x, const float* __restrict__ Wg,
                            int* __restrict__ idx, float* __restrict__ gw) {
    int t = blockIdx.x;
    int warp = threadIdx.x >> 5, lane = threadIdx.x & 31;
    const float* xr = x + (size_t)t * DM;
    float s = 0.f;
    #pragma unroll 4
    for (int d = lane; d < DM; d += 32) s += xr[d] * Wg[d * NE + warp];
    #pragma unroll
    for (int o = 16; o; o >>= 1) s += __shfl_xor_sync(0xffffffffu, s, o);
    __shared__ float logits[NE];
    if (lane == 0) logits[warp] = s;
    __syncthreads();
    if (threadIdx.x == 0) {
        float best = logits[0]; int bi = 0;
        #pragma unroll
        for (int e = 1; e < NE; e++) if (logits[e] > best) { best = logits[e]; bi = e; }
        float sum = 0.f;
        #pragma unroll
        for (int e = 0; e < NE; e++) sum += expf(logits[e] - best);
        idx[t] = bi;
        gw[t] = 1.f / sum;
    }
}

// ---------------- scatter: group tokens by expert into 128-aligned segments ----------------
__global__ void scatter_kernel(const int* __restrict__ idx, int* __restrict__ perm,
                               int* __restrict__ tile_expert) {
    __shared__ int cnt[NE];
    __shared__ int cur[NE];
    int tid = threadIdx.x;
    if (tid < NE) cnt[tid] = 0;
    for (int i = tid; i < PADROWS; i += blockDim.x) perm[i] = -1;
    __syncthreads();
    for (int t = tid; t < TKN; t += blockDim.x) atomicAdd(&cnt[idx[t]], 1);
    __syncthreads();
    if (tid == 0) {
        int c = 0;
        for (int e = 0; e < NE; e++) {
            cur[e] = c;
            int tiles = (cnt[e] + 127) >> 7;
            for (int i = 0; i < tiles; i++) tile_expert[(c >> 7) + i] = e;
            c += tiles << 7;
        }
        for (int i = c >> 7; i < MAXTILES; i++) tile_expert[i] = -1;
    }
    __syncthreads();
    for (int t = tid; t < TKN; t += blockDim.x) {
        int p = atomicAdd(&cur[idx[t]], 1);
        perm[p] = t;
    }
}

// ============ tf32 mma.sync MoE GEMM (unchanged from R6 passing version) ============
#define KSTRIDE 136
#define STGW (16 * KSTRIDE)

__global__ void __launch_bounds__(256, 2)
moe_gemm_mma(const float* __restrict__ In, const float* __restrict__ W,
             const float* __restrict__ bias, const float* __restrict__ gw,
             const int* __restrict__ perm, const int* __restrict__ tile_expert,
             float* __restrict__ Out, int K, int Nout, int gelu_flag) {
    int e = tile_expert[blockIdx.y];
    if (e < 0) return;
    __shared__ uint32_t SA[2][STGW];
    __shared__ uint32_t SB[2][STGW];

    int tid = threadIdx.x, wid = tid >> 5, lane = tid & 31;
    int g = lane >> 2, tg = lane & 3;
    int warp_m = wid & 3, warp_n = wid >> 2;
    int row0 = blockIdx.y << 7, col0 = blockIdx.x << 7;

    int mS = tid & 127;
    int kqS = (tid >> 7) << 3;
    int tokA = perm[row0 + mS];
    const float* aptr = (tokA >= 0) ? (In + (size_t)tokA * K + kqS) : In;
    int kBs = tid >> 4;
    int nBs = (tid & 15) << 3;
    const float* bptr = W + ((size_t)e * K + kBs) * Nout + col0 + nBs;

    float acc[2][8][4];
    #pragma unroll
    for (int mi = 0; mi < 2; mi++)
        #pragma unroll
        for (int ni = 0; ni < 8; ni++)
            #pragma unroll
            for (int q = 0; q < 4; q++) acc[mi][ni][q] = 0.f;

    int nchunk = K >> 4;

    {
        float4 av0 = make_float4(0.f,0.f,0.f,0.f), av1 = av0;
        if (tokA >= 0) { av0 = *(const float4*)(aptr); av1 = *(const float4*)(aptr + 4); }
        float4 bv0 = *(const float4*)(bptr);
        float4 bv1 = *(const float4*)(bptr + 4);
        SA[0][(kqS + 0) * KSTRIDE + mS] = f2tf32(av0.x);
        SA[0][(kqS + 1) * KSTRIDE + mS] = f2tf32(av0.y);
        SA[0][(kqS + 2) * KSTRIDE + mS] = f2tf32(av0.z);
        SA[0][(kqS + 3) * KSTRIDE + mS] = f2tf32(av0.w);
        SA[0][(kqS + 4) * KSTRIDE + mS] = f2tf32(av1.x);
        SA[0][(kqS + 5) * KSTRIDE + mS] = f2tf32(av1.y);
        SA[0][(kqS + 6) * KSTRIDE + mS] = f2tf32(av1.z);
        SA[0][(kqS + 7) * KSTRIDE + mS] = f2tf32(av1.w);
        uint32_t* bdst = &SB[0][kBs * KSTRIDE + nBs];
        bdst[0] = f2tf32(bv0.x); bdst[1] = f2tf32(bv0.y);
        bdst[2] = f2tf32(bv0.z); bdst[3] = f2tf32(bv0.w);
        bdst[4] = f2tf32(bv1.x); bdst[5] = f2tf32(bv1.y);
        bdst[6] = f2tf32(bv1.z); bdst[7] = f2tf32(bv1.w);
    }
    __syncthreads();

    int am0 = warp_m * 32 + g;
    int bn0 = warp_n * 64 + g;

    for (int c = 0; c < nchunk; c++) {
        int buf = c & 1;
        bool has_next = (c + 1) < nchunk;
        float4 av0, av1, bv0, bv1;
        if (has_next) {
            int k0 = (c + 1) << 4;
            if (tokA >= 0) {
                av0 = *(const float4*)(aptr + k0);
                av1 = *(const float4*)(aptr + k0 + 4);
            } else { av0 = make_float4(0.f,0.f,0.f,0.f); av1 = av0; }
            const float* bp = bptr + (size_t)k0 * Nout;
            bv0 = *(const float4*)(bp);
            bv1 = *(const float4*)(bp + 4);
        }

        const uint32_t* Ab = SA[buf];
        const uint32_t* Bb = SB[buf];
        #pragma unroll
        for (int ks = 0; ks < 2; ks++) {
            int kb = ks << 3;
            uint32_t a[2][4];
            #pragma unroll
            for (int mi = 0; mi < 2; mi++) {
                int m = am0 + mi * 16;
                a[mi][0] = Ab[(kb + tg) * KSTRIDE + m];
                a[mi][1] = Ab[(kb + tg) * KSTRIDE + m + 8];
                a[mi][2] = Ab[(kb + tg + 4) * KSTRIDE + m];
                a[mi][3] = Ab[(kb + tg + 4) * KSTRIDE + m + 8];
            }
            #pragma unroll
            for (int ni = 0; ni < 8; ni++) {
                int n = bn0 + ni * 8;
                uint32_t b0 = Bb[(kb + tg) * KSTRIDE + n];
                uint32_t b1 = Bb[(kb + tg + 4) * KSTRIDE + n];
                mma_tf32(acc[0][ni][0], acc[0][ni][1], acc[0][ni][2], acc[0][ni][3],
                         a[0][0], a[0][1], a[0][2], a[0][3], b0, b1);
                mma_tf32(acc[1][ni][0], acc[1][ni][1], acc[1][ni][2], acc[1][ni][3],
                         a[1][0], a[1][1], a[1][2], a[1][3], b0, b1);
            }
        }

        if (has_next) {
            int nb = buf ^ 1;
            SA[nb][(kqS + 0) * KSTRIDE + mS] = f2tf32(av0.x);
            SA[nb][(kqS + 1) * KSTRIDE + mS] = f2tf32(av0.y);
            SA[nb][(kqS + 2) * KSTRIDE + mS] = f2tf32(av0.z);
            SA[nb][(kqS + 3) * KSTRIDE + mS] = f2tf32(av0.w);
            SA[nb][(kqS + 4) * KSTRIDE + mS] = f2tf32(av1.x);
            SA[nb][(kqS + 5) * KSTRIDE + mS] = f2tf32(av1.y);
            SA[nb][(kqS + 6) * KSTRIDE + mS] = f2tf32(av1.z);
            SA[nb][(kqS + 7) * KSTRIDE + mS] = f2tf32(av1.w);
            uint32_t* bdst = &SB[nb][kBs * KSTRIDE + nBs];
            bdst[0] = f2tf32(bv0.x); bdst[1] = f2tf32(bv0.y);
            bdst[2] = f2tf32(bv0.z); bdst[3] = f2tf32(bv0.w);
            bdst[4] = f2tf32(bv1.x); bdst[5] = f2tf32(bv1.y);
            bdst[6] = f2tf32(bv1.z); bdst[7] = f2tf32(bv1.w);
            __syncthreads();
        }
    }

    int tok[4]; float gwv[4];
    #pragma unroll
    for (int q = 0; q < 4; q++) {
        int r = row0 + warp_m * 32 + g + q * 8;
        tok[q] = perm[r];
        gwv[q] = (tok[q] >= 0) ? gw[tok[q]] : 0.f;
    }
    #pragma unroll
    for (int ni = 0; ni < 8; ni++) {
        int col = col0 + warp_n * 64 + ni * 8 + 2 * tg;
        float2 bs2 = *(const float2*)&bias[(size_t)e * Nout + col];
        #pragma unroll
        for (int mi = 0; mi < 2; mi++) {
            #pragma unroll
            for (int half = 0; half < 2; half++) {
                int q = mi * 2 + half;
                if (tok[q] < 0) continue;
                float v0 = (acc[mi][ni][half * 2 + 0] + bs2.x) * gwv[q];
                float v1 = (acc[mi][ni][half * 2 + 1] + bs2.y) * gwv[q];
                if (gelu_flag) {
                    float c0 = v0 + 0.044715f * v0 * v0 * v0;
                    v0 = 0.5f * v0 * (1.f + tanhf(0.7978845608028654f * c0));
                    float c1 = v1 + 0.044715f * v1 * v1 * v1;
                    v1 = 0.5f * v1 * (1.f + tanhf(0.7978845608028654f * c1));
                }
                *(float2*)&Out[(size_t)tok[q] * Nout + col] = make_float2(v0, v1);
            }
        }
    }
}

// ============ flash attention v2: m16n8k8 tf32 MMA, BQ=64, BK=64 ============
// 8 warps: warp_m (0..3) x warp_n (0..1). S warp tile 16x32; O warp tile 16x32.
// smem stride 68 floats: fragment LDS banks = (4g + tg) distinct -> conflict-free.
#define ASTR 68
#define ATT2_SMEM_WORDS (4 * 64 * ASTR + 128 + 128 + 64)

__global__ void __launch_bounds__(256)
attn_mma(const float* __restrict__ qkv, const unsigned char* __restrict__ mask,
         float* __restrict__ ctx) {
    extern __shared__ uint32_t sm4[];
    uint32_t* Qs = sm4;                    // [64][68] q-major, tf32
    uint32_t* Ks = Qs + 64 * ASTR;         // [64][68] key-major (col-major B)
    uint32_t* Vt = Ks + 64 * ASTR;         // [64][68] d-major (V transposed)
    uint32_t* Ps = Vt + 64 * ASTR;         // [64][68] q-major, tf32
    float* redm  = (float*)(Ps + 64 * ASTR);  // [2][64]
    float* redl  = redm + 128;                // [2][64]
    float* maskS = redl + 128;                // [64]

    int bh = blockIdx.y;
    int b = bh >> 4, h = bh & 15;
    int n0 = blockIdx.x << 6;
    int tid = threadIdx.x, lane = tid & 31, wid = tid >> 5;
    int g = lane >> 2, tg = lane & 3;
    int warp_m = wid & 3, warp_n = wid >> 2;
    int row0 = warp_m * 16 + g, row1 = row0 + 8;

    // loader mapping: row = tid&63, d-segment = (tid>>6)*16
    int lrow = tid & 63, d0 = (tid >> 6) << 4;

    // ---- load Q tile once ----
    {
        const float* qp = qkv + (size_t)(b * 1024 + n0 + lrow) * 3072 + h * 64 + d0;
        #pragma unroll
        for (int i = 0; i < 16; i += 4) {
            float4 v = *(const float4*)(qp + i);
            *(uint4*)&Qs[lrow * ASTR + d0 + i] =
                make_uint4(f2tf32(v.x), f2tf32(v.y), f2tf32(v.z), f2tf32(v.w));
        }
    }

    float o[4][4];
    #pragma unroll
    for (int ni = 0; ni < 4; ni++)
        #pragma unroll
        for (int q = 0; q < 4; q++) o[ni][q] = 0.f;
    float m0 = -1e30f, m1 = -1e30f, l0 = 0.f, l1 = 0.f;

    for (int kt = 0; kt < 16; kt++) {
        // ---- load K (key-major) and V (transposed, d-major) ----
        {
            const float* base = qkv + (size_t)(b * 1024 + kt * 64 + lrow) * 3072 + h * 64 + d0;
            #pragma unroll
            for (int i = 0; i < 16; i += 4) {
                float4 kv = *(const float4*)(base + 1024 + i);
                *(uint4*)&Ks[lrow * ASTR + d0 + i] =
                    make_uint4(f2tf32(kv.x), f2tf32(kv.y), f2tf32(kv.z), f2tf32(kv.w));
            }
            #pragma unroll
            for (int i = 0; i < 16; i += 4) {
                float4 vv = *(const float4*)(base + 2048 + i);
                Vt[(d0 + i + 0) * ASTR + lrow] = f2tf32(vv.x);
                Vt[(d0 + i + 1) * ASTR + lrow] = f2tf32(vv.y);
                Vt[(d0 + i + 2) * ASTR + lrow] = f2tf32(vv.z);
                Vt[(d0 + i + 3) * ASTR + lrow] = f2tf32(vv.w);
            }
            if (tid < 64)
                maskS[tid] = mask[b * 1024 + kt * 64 + tid] ? -10000.f : 0.f;
        }
        __syncthreads();

        // ---- S = Q K^T (scaled later) ----
        float s[4][4];
        #pragma unroll
        for (int ni = 0; ni < 4; ni++)
            #pragma unroll
            for (int q = 0; q < 4; q++) s[ni][q] = 0.f;
        #pragma unroll
        for (int kb = 0; kb < 64; kb += 8) {
            uint32_t a0 = Qs[row0 * ASTR + kb + tg];
            uint32_t a1 = Qs[row1 * ASTR + kb + tg];
            uint32_t a2 = Qs[row0 * ASTR + kb + tg + 4];
            uint32_t a3 = Qs[row1 * ASTR + kb + tg + 4];
            #pragma unroll
            for (int ni = 0; ni < 4; ni++) {
                int n = warp_n * 32 + ni * 8 + g;
                uint32_t b0 = Ks[n * ASTR + kb + tg];
                uint32_t b1 = Ks[n * ASTR + kb + tg + 4];
                mma_tf32(s[ni][0], s[ni][1], s[ni][2], s[ni][3], a0, a1, a2, a3, b0, b1);
            }
        }
        // scale + mask
        #pragma unroll
        for (int ni = 0; ni < 4; ni++) {
            int c0 = warp_n * 32 + ni * 8 + 2 * tg;
            float mv0 = maskS[c0], mv1 = maskS[c0 + 1];
            s[ni][0] = s[ni][0] * 0.125f + mv0;
            s[ni][1] = s[ni][1] * 0.125f + mv1;
            s[ni][2] = s[ni][2] * 0.125f + mv0;
            s[ni][3] = s[ni][3] * 0.125f + mv1;
        }

        // ---- row max (quad shuffle + cross-warp_n smem) ----
        float rm0 = -1e30f, rm1 = -1e30f;
        #pragma unroll
        for (int ni = 0; ni < 4; ni++) {
            rm0 = fmaxf(rm0, fmaxf(s[ni][0], s[ni][1]));
            rm1 = fmaxf(rm1, fmaxf(s[ni][2], s[ni][3]));
        }
        rm0 = fmaxf(rm0, __shfl_xor_sync(0xffffffffu, rm0, 1));
        rm0 = fmaxf(rm0, __shfl_xor_sync(0xffffffffu, rm0, 2));
        rm1 = fmaxf(rm1, __shfl_xor_sync(0xffffffffu, rm1, 1));
        rm1 = fmaxf(rm1, __shfl_xor_sync(0xffffffffu, rm1, 2));
        if (tg == 0) {
            redm[warp_n * 64 + row0] = rm0;
            redm[warp_n * 64 + row1] = rm1;
        }
        __syncthreads();
        float mn0 = fmaxf(m0, fmaxf(redm[row0], redm[64 + row0]));
        float mn1 = fmaxf(m1, fmaxf(redm[row1], redm[64 + row1]));
        float sc0 = __expf(m0 - mn0), sc1 = __expf(m1 - mn1);
        m0 = mn0; m1 = mn1;

        // ---- p = exp(s - m), write P (tf32), partial row sums ----
        float ps0 = 0.f, ps1 = 0.f;
        #pragma unroll
        for (int ni = 0; ni < 4; ni++) {
            int c0 = warp_n * 32 + ni * 8 + 2 * tg;
            s[ni][0] = __expf(s[ni][0] - mn0);
            s[ni][1] = __expf(s[ni][1] - mn0);
            s[ni][2] = __expf(s[ni][2] - mn1);
            s[ni][3] = __expf(s[ni][3] - mn1);
            ps0 += s[ni][0] + s[ni][1];
            ps1 += s[ni][2] + s[ni][3];
            Ps[row0 * ASTR + c0]     = f2tf32(s[ni][0]);
            Ps[row0 * ASTR + c0 + 1] = f2tf32(s[ni][1]);
            Ps[row1 * ASTR + c0]     = f2tf32(s[ni][2]);
            Ps[row1 * ASTR + c0 + 1] = f2tf32(s[ni][3]);
        }
        ps0 += __shfl_xor_sync(0xffffffffu, ps0, 1);
        ps0 += __shfl_xor_sync(0xffffffffu, ps0, 2);
        ps1 += __shfl_xor_sync(0xffffffffu, ps1, 1);
        ps1 += __shfl_xor_sync(0xffffffffu, ps1, 2);
        if (tg == 0) {
            redl[warp_n * 64 + row0] = ps0;
            redl[warp_n * 64 + row1] = ps1;
        }
        // rescale O accumulators
        #pragma unroll
        for (int ni = 0; ni < 4; ni++) {
            o[ni][0] *= sc0; o[ni][1] *= sc0;
            o[ni][2] *= sc1; o[ni][3] *= sc1;
        }
        __syncthreads();
        l0 = l0 * sc0 + redl[row0] + redl[64 + row0];
        l1 = l1 * sc1 + redl[row1] + redl[64 + row1];

        // ---- O += P V (A = Ps row-major, B = Vt col-major over kk) ----
        #pragma unroll
        for (int kb = 0; kb < 64; kb += 8) {
            uint32_t a0 = Ps[row0 * ASTR + kb + tg];
            uint32_t a1 = Ps[row1 * ASTR + kb + tg];
            uint32_t a2 = Ps[row0 * ASTR + kb + tg + 4];
            uint32_t a3 = Ps[row1 * ASTR + kb + tg + 4];
            #pragma unroll
            for (int ni = 0; ni < 4; ni++) {
                int n = warp_n * 32 + ni * 8 + g;   // d index
                uint32_t b0 = Vt[n * ASTR + kb + tg];
                uint32_t b1 = Vt[n * ASTR + kb + tg + 4];
                mma_tf32(o[ni][0], o[ni][1], o[ni][2], o[ni][3], a0, a1, a2, a3, b0, b1);
            }
        }
        __syncthreads();   // protect Ks/Vt/maskS (and Ps) before next iteration's stores
    }

    // ---- write ctx ----
    float inv0 = 1.f / l0, inv1 = 1.f / l1;
    int t0 = b * 1024 + n0 + row0;
    int t1 = b * 1024 + n0 + row1;
    #pragma unroll
    for (int ni = 0; ni < 4; ni++) {
        int c = warp_n * 32 + ni * 8 + 2 * tg;
        *(float2*)&ctx[(size_t)t0 * 1024 + h * 64 + c] =
            make_float2(o[ni][0] * inv0, o[ni][1] * inv0);
        *(float2*)&ctx[(size_t)t1 * 1024 + h * 64 + c] =
            make_float2(o[ni][2] * inv1, o[ni][3] * inv1);
    }
}

// ---------------- residual + layernorm ----------------
__global__ void __launch_bounds__(256)
ln_kernel(const float* __restrict__ a, const float* __restrict__ b,
          const float* __restrict__ s, const float* __restrict__ bias,
          float* __restrict__ out) {
    int t = blockIdx.x;
    int base = threadIdx.x << 2;
    const float* ar = a + (size_t)t * DM;
    const float* br = b + (size_t)t * DM;
    float4 av = *(const float4*)(ar + base);
    float4 bv = *(const float4*)(br + base);
    float v[4] = {av.x + bv.x, av.y + bv.y, av.z + bv.z, av.w + bv.w};
    float s1 = v[0] + v[1] + v[2] + v[3];
    float s2 = v[0] * v[0] + v[1] * v[1] + v[2] * v[2] + v[3] * v[3];
    #pragma unroll
    for (int o = 16; o; o >>= 1) {
        s1 += __shfl_xor_sync(0xffffffffu, s1, o);
        s2 += __shfl_xor_sync(0xffffffffu, s2, o);
    }
    __shared__ float w1[8], w2[8];
    __shared__ float sh_mean, sh_inv;
    int warp = threadIdx.x >> 5, lane = threadIdx.x & 31;
    if (lane == 0) { w1[warp] = s1; w2[warp] = s2; }
    __syncthreads();
    if (threadIdx.x == 0) {
        float A = 0.f, B = 0.f;
        #pragma unroll
        for (int i = 0; i < 8; i++) { A += w1[i]; B += w2[i]; }
        float mean = A * (1.f / DM);
        float var = B * (1.f / DM) - mean * mean;
        sh_mean = mean;
        sh_inv = rsqrtf(var + 1e-5f);
    }
    __syncthreads();
    float mean = sh_mean, inv = sh_inv;
    float4 sv = *(const float4*)(s + base);
    float4 biv = *(const float4*)(bias + base);
    float4 ov;
    ov.x = (v[0] - mean) * inv * sv.x + biv.x;
    ov.y = (v[1] - mean) * inv * sv.y + biv.y;
    ov.z = (v[2] - mean) * inv * sv.z + biv.z;
    ov.w = (v[3] - mean) * inv * sv.w + biv.w;
    *(float4*)(out + (size_t)t * DM + base) = ov;
}

// ---------------- launch ----------------
extern "C" void kernel_launch(void* const* d_in, const int* in_sizes, int n_in,
                              void* d_out, int out_size) {
    const float* src     = (const float*)d_in[0];
    const unsigned char* mask = (const unsigned char*)d_in[1];
    const float* Wg_attn = (const float*)d_in[2];
    const float* Wqkv    = (const float*)d_in[3];
    const float* bqkv    = (const float*)d_in[4];
    const float* Wo      = (const float*)d_in[5];
    const float* bo      = (const float*)d_in[6];
    const float* Wg_ffn  = (const float*)d_in[7];
    const float* W1      = (const float*)d_in[8];
    const float* b1      = (const float*)d_in[9];
    const float* W2      = (const float*)d_in[10];
    const float* b2      = (const float*)d_in[11];
    const float* ln1_s   = (const float*)d_in[12];
    const float* ln1_b   = (const float*)d_in[13];
    const float* ln2_s   = (const float*)d_in[14];
    const float* ln2_b   = (const float*)d_in[15];
    float* out = (float*)d_out;

    float *qkv, *ctx, *x, *tmp, *hbuf, *gw0, *gw1;
    int *idx0, *idx1, *perm0, *perm1, *te0, *te1;
    cudaGetSymbolAddress((void**)&qkv,  g_qkv);
    cudaGetSymbolAddress((void**)&ctx,  g_ctx);
    cudaGetSymbolAddress((void**)&x,    g_x);
    cudaGetSymbolAddress((void**)&tmp,  g_tmp);
    cudaGetSymbolAddress((void**)&hbuf, g_h);
    cudaGetSymbolAddress((void**)&gw0,  g_gw0);
    cudaGetSymbolAddress((void**)&gw1,  g_gw1);
    cudaGetSymbolAddress((void**)&idx0, g_idx0);
    cudaGetSymbolAddress((void**)&idx1, g_idx1);
    cudaGetSymbolAddress((void**)&perm0, g_perm0);
    cudaGetSymbolAddress((void**)&perm1, g_perm1);
    cudaGetSymbolAddress((void**)&te0,  g_te0);
    cudaGetSymbolAddress((void**)&te1,  g_te1);

    int att_smem = ATT2_SMEM_WORDS * (int)sizeof(uint32_t);
    cudaFuncSetAttribute(attn_mma, cudaFuncAttributeMaxDynamicSharedMemorySize, att_smem);

    // 1. attention gate + grouping
    gate_kernel<<<TKN, 256>>>(src, Wg_attn, idx0, gw0);
    scatter_kernel<<<1, 256>>>(idx0, perm0, te0);
    // 2. QKV projection (tf32 mma)
    moe_gemm_mma<<<dim3(3 * DM / 128, MAXTILES), 256>>>(
        src, Wqkv, bqkv, gw0, perm0, te0, qkv, DM, 3 * DM, 0);
    // 3. attention (tf32 mma)
    attn_mma<<<dim3(1024 / 64, 2 * NH), 256, att_smem>>>(qkv, mask, ctx);
    // 4. output projection
    moe_gemm_mma<<<dim3(DM / 128, MAXTILES), 256>>>(
        ctx, Wo, bo, gw0, perm0, te0, tmp, DM, DM, 0);
    // 5. x = LN1(src + attn_out)
    ln_kernel<<<TKN, 256>>>(src, tmp, ln1_s, ln1_b, x);
    // 6. ffn gate + grouping
    gate_kernel<<<TKN, 256>>>(x, Wg_ffn, idx1, gw1);
    scatter_kernel<<<1, 256>>>(idx1, perm1, te1);
    // 7. h = gelu(gated W1)
    moe_gemm_mma<<<dim3(FFD / 128, MAXTILES), 256>>>(
        x, W1, b1, gw1, perm1, te1, hbuf, DM, FFD, 1);
    // 8. ffn = gated W2
    moe_gemm_mma<<<dim3(FFD / 512, MAXTILES) /* 8 */, 256>>>(
        hbuf, W2, b2, gw1, perm1, te1, tmp, FFD, DM, 0);
    // 9. out = LN2(x + ffn)
    ln_kernel<<<TKN, 256>>>(x, tmp, ln2_s, ln2_b, out);
}

// round 8
// speedup vs baseline: 1.2945x; 1.1312x over previous
#include <cuda_runtime.h>
#include <math.h>
#include <stdint.h>

// Problem constants
#define TKN 2048          // B*N tokens
#define DM 1024           // model dim
#define NE 8              // experts
#define FFD 4096          // ffn dim
#define NH 16             // heads
#define HD 64             // head dim
#define PADROWS 3072      // token rows padded to 128 per expert segment
#define MAXTILES 24       // PADROWS/128

// ---------------- scratch (device globals; no allocation allowed) ----------------
__device__ float g_qkv[TKN * 3 * DM];
__device__ float g_ctx[TKN * DM];
__device__ float g_x[TKN * DM];
__device__ float g_tmp[4 * TKN * DM];     // up to 4 split-K partials
__device__ float g_h[TKN * FFD];
__device__ int   g_idx0[TKN];
__device__ int   g_idx1[TKN];
__device__ float g_gw0[TKN];
__device__ float g_gw1[TKN];
__device__ int   g_perm0[PADROWS];
__device__ int   g_perm1[PADROWS];
__device__ int   g_te0[MAXTILES];
__device__ int   g_te1[MAXTILES];

__device__ __forceinline__ uint32_t f2tf32(float x) {
    uint32_t r;
    asm("cvt.rna.tf32.f32 %0, %1;" : "=r"(r) : "f"(x));
    return r;
}
__device__ __forceinline__ void mma_tf32(float& c0, float& c1, float& c2, float& c3,
                                         uint32_t a0, uint32_t a1, uint32_t a2, uint32_t a3,
                                         uint32_t b0, uint32_t b1) {
    asm volatile(
        "mma.sync.aligned.m16n8k8.row.col.f32.tf32.tf32.f32 "
        "{%0,%1,%2,%3}, {%4,%5,%6,%7}, {%8,%9}, {%0,%1,%2,%3};"
        : "+f"(c0), "+f"(c1), "+f"(c2), "+f"(c3)
        : "r"(a0), "r"(a1), "r"(a2), "r"(a3), "r"(b0), "r"(b1));
}

// ---------------- gate: logits = x @ Wg [D,E], softmax, top-1 ----------------
__global__ void gate_kernel(const float* __restrict__ x, const float* __restrict__ Wg,
                            int* __restrict__ idx, float* __restrict__ gw) {
    int t = blockIdx.x;
    int warp = threadIdx.x >> 5, lane = threadIdx.x & 31;
    const float* xr = x + (size_t)t * DM;
    float s = 0.f;
    #pragma unroll 4
    for (int d = lane; d < DM; d += 32) s += xr[d] * Wg[d * NE + warp];
    #pragma unroll
    for (int o = 16; o; o >>= 1) s += __shfl_xor_sync(0xffffffffu, s, o);
    __shared__ float logits[NE];
    if (lane == 0) logits[warp] = s;
    __syncthreads();
    if (threadIdx.x == 0) {
        float best = logits[0]; int bi = 0;
        #pragma unroll
        for (int e = 1; e < NE; e++) if (logits[e] > best) { best = logits[e]; bi = e; }
        float sum = 0.f;
        #pragma unroll
        for (int e = 0; e < NE; e++) sum += expf(logits[e] - best);
        idx[t] = bi;
        gw[t] = 1.f / sum;
    }
}

// ---------------- scatter: group tokens by expert into 128-aligned segments ----------------
__global__ void scatter_kernel(const int* __restrict__ idx, int* __restrict__ perm,
                               int* __restrict__ tile_expert) {
    __shared__ int cnt[NE];
    __shared__ int cur[NE];
    int tid = threadIdx.x;
    if (tid < NE) cnt[tid] = 0;
    for (int i = tid; i < PADROWS; i += blockDim.x) perm[i] = -1;
    __syncthreads();
    for (int t = tid; t < TKN; t += blockDim.x) atomicAdd(&cnt[idx[t]], 1);
    __syncthreads();
    if (tid == 0) {
        int c = 0;
        for (int e = 0; e < NE; e++) {
            cur[e] = c;
            int tiles = (cnt[e] + 127) >> 7;
            for (int i = 0; i < tiles; i++) tile_expert[(c >> 7) + i] = e;
            c += tiles << 7;
        }
        for (int i = c >> 7; i < MAXTILES; i++) tile_expert[i] = -1;
    }
    __syncthreads();
    for (int t = tid; t < TKN; t += blockDim.x) {
        int p = atomicAdd(&cur[idx[t]], 1);
        perm[p] = t;
    }
}

// ============ tf32 mma.sync MoE GEMM with split-K ============
// 128x128 CTA tile, BK=16, 8 warps (4M x 2N), warp tile 32x64, m16n8k8 tf32.
// blockIdx.z = K-slice; slice z writes Out + z*TKN*Nout; bias only on z==0.
// B smem stores are vectorized STS.128, conflict-free.
#define KSTRIDE 136
#define STGW (16 * KSTRIDE)

__global__ void __launch_bounds__(256, 2)
moe_gemm_mma(const float* __restrict__ In, const float* __restrict__ W,
             const float* __restrict__ bias, const float* __restrict__ gw,
             const int* __restrict__ perm, const int* __restrict__ tile_expert,
             float* __restrict__ Out, int Ktot, int Nout, int gelu_flag, int klen) {
    int e = tile_expert[blockIdx.y];
    if (e < 0) return;
    __shared__ uint32_t SA[2][STGW];
    __shared__ uint32_t SB[2][STGW];

    int tid = threadIdx.x, wid = tid >> 5, lane = tid & 31;
    int g = lane >> 2, tg = lane & 3;
    int warp_m = wid & 3, warp_n = wid >> 2;
    int row0 = blockIdx.y << 7, col0 = blockIdx.x << 7;
    int k0off = blockIdx.z * klen;
    float* OutZ = Out + (size_t)blockIdx.z * TKN * Nout;
    float bsel = (blockIdx.z == 0) ? 1.f : 0.f;

    // ---- global load mappings ----
    // A: thread handles row mS (0..127), k-half kqS (0 or 8) of each 16-chunk
    int mS = tid & 127;
    int kqS = (tid >> 7) << 3;
    int tokA = perm[row0 + mS];
    const float* aptr = (tokA >= 0) ? (In + (size_t)tokA * Ktot + k0off + kqS) : In;
    // B: thread handles k rows k2,k2+1 (k2 = (tid>>5)*2), 4 cols at nB4
    int k2 = (tid >> 5) << 1;
    int nB4 = (tid & 31) << 2;
    const float* bptr = W + ((size_t)e * Ktot + k0off + k2) * Nout + col0 + nB4;

    float acc[2][8][4];
    #pragma unroll
    for (int mi = 0; mi < 2; mi++)
        #pragma unroll
        for (int ni = 0; ni < 8; ni++)
            #pragma unroll
            for (int q = 0; q < 4; q++) acc[mi][ni][q] = 0.f;

    int nchunk = klen >> 4;

    // ---- prologue: chunk 0 into buffer 0 ----
    {
        float4 av0 = make_float4(0.f,0.f,0.f,0.f), av1 = av0;
        if (tokA >= 0) { av0 = *(const float4*)(aptr); av1 = *(const float4*)(aptr + 4); }
        float4 bv0 = *(const float4*)(bptr);
        float4 bv1 = *(const float4*)(bptr + Nout);
        SA[0][(kqS + 0) * KSTRIDE + mS] = f2tf32(av0.x);
        SA[0][(kqS + 1) * KSTRIDE + mS] = f2tf32(av0.y);
        SA[0][(kqS + 2) * KSTRIDE + mS] = f2tf32(av0.z);
        SA[0][(kqS + 3) * KSTRIDE + mS] = f2tf32(av0.w);
        SA[0][(kqS + 4) * KSTRIDE + mS] = f2tf32(av1.x);
        SA[0][(kqS + 5) * KSTRIDE + mS] = f2tf32(av1.y);
        SA[0][(kqS + 6) * KSTRIDE + mS] = f2tf32(av1.z);
        SA[0][(kqS + 7) * KSTRIDE + mS] = f2tf32(av1.w);
        *(uint4*)&SB[0][k2 * KSTRIDE + nB4] =
            make_uint4(f2tf32(bv0.x), f2tf32(bv0.y), f2tf32(bv0.z), f2tf32(bv0.w));
        *(uint4*)&SB[0][(k2 + 1) * KSTRIDE + nB4] =
            make_uint4(f2tf32(bv1.x), f2tf32(bv1.y), f2tf32(bv1.z), f2tf32(bv1.w));
    }
    __syncthreads();

    int am0 = warp_m * 32 + g;
    int bn0 = warp_n * 64 + g;

    for (int c = 0; c < nchunk; c++) {
        int buf = c & 1;
        bool has_next = (c + 1) < nchunk;
        float4 av0, av1, bv0, bv1;
        if (has_next) {
            int k0 = (c + 1) << 4;
            if (tokA >= 0) {
                av0 = *(const float4*)(aptr + k0);
                av1 = *(const float4*)(aptr + k0 + 4);
            } else { av0 = make_float4(0.f,0.f,0.f,0.f); av1 = av0; }
            const float* bp = bptr + (size_t)k0 * Nout;
            bv0 = *(const float4*)(bp);
            bv1 = *(const float4*)(bp + Nout);
        }

        // ---- compute chunk c ----
        const uint32_t* Ab = SA[buf];
        const uint32_t* Bb = SB[buf];
        #pragma unroll
        for (int ks = 0; ks < 2; ks++) {
            int kb = ks << 3;
            uint32_t a[2][4];
            #pragma unroll
            for (int mi = 0; mi < 2; mi++) {
                int m = am0 + mi * 16;
                a[mi][0] = Ab[(kb + tg) * KSTRIDE + m];
                a[mi][1] = Ab[(kb + tg) * KSTRIDE + m + 8];
                a[mi][2] = Ab[(kb + tg + 4) * KSTRIDE + m];
                a[mi][3] = Ab[(kb + tg + 4) * KSTRIDE + m + 8];
            }
            #pragma unroll
            for (int ni = 0; ni < 8; ni++) {
                int n = bn0 + ni * 8;
                uint32_t b0 = Bb[(kb + tg) * KSTRIDE + n];
                uint32_t b1 = Bb[(kb + tg + 4) * KSTRIDE + n];
                mma_tf32(acc[0][ni][0], acc[0][ni][1], acc[0][ni][2], acc[0][ni][3],
                         a[0][0], a[0][1], a[0][2], a[0][3], b0, b1);
                mma_tf32(acc[1][ni][0], acc[1][ni][1], acc[1][ni][2], acc[1][ni][3],
                         a[1][0], a[1][1], a[1][2], a[1][3], b0, b1);
            }
        }

        if (has_next) {
            int nb = buf ^ 1;
            SA[nb][(kqS + 0) * KSTRIDE + mS] = f2tf32(av0.x);
            SA[nb][(kqS + 1) * KSTRIDE + mS] = f2tf32(av0.y);
            SA[nb][(kqS + 2) * KSTRIDE + mS] = f2tf32(av0.z);
            SA[nb][(kqS + 3) * KSTRIDE + mS] = f2tf32(av0.w);
            SA[nb][(kqS + 4) * KSTRIDE + mS] = f2tf32(av1.x);
            SA[nb][(kqS + 5) * KSTRIDE + mS] = f2tf32(av1.y);
            SA[nb][(kqS + 6) * KSTRIDE + mS] = f2tf32(av1.z);
            SA[nb][(kqS + 7) * KSTRIDE + mS] = f2tf32(av1.w);
            *(uint4*)&SB[nb][k2 * KSTRIDE + nB4] =
                make_uint4(f2tf32(bv0.x), f2tf32(bv0.y), f2tf32(bv0.z), f2tf32(bv0.w));
            *(uint4*)&SB[nb][(k2 + 1) * KSTRIDE + nB4] =
                make_uint4(f2tf32(bv1.x), f2tf32(bv1.y), f2tf32(bv1.z), f2tf32(bv1.w));
            __syncthreads();
        }
    }

    // ---- epilogue ----
    int tok[4]; float gwv[4];
    #pragma unroll
    for (int q = 0; q < 4; q++) {
        int r = row0 + warp_m * 32 + g + q * 8;
        tok[q] = perm[r];
        gwv[q] = (tok[q] >= 0) ? gw[tok[q]] : 0.f;
    }
    #pragma unroll
    for (int ni = 0; ni < 8; ni++) {
        int col = col0 + warp_n * 64 + ni * 8 + 2 * tg;
        float2 bs2 = *(const float2*)&bias[(size_t)e * Nout + col];
        bs2.x *= bsel; bs2.y *= bsel;
        #pragma unroll
        for (int mi = 0; mi < 2; mi++) {
            #pragma unroll
            for (int half = 0; half < 2; half++) {
                int q = mi * 2 + half;
                if (tok[q] < 0) continue;
                float v0 = (acc[mi][ni][half * 2 + 0] + bs2.x) * gwv[q];
                float v1 = (acc[mi][ni][half * 2 + 1] + bs2.y) * gwv[q];
                if (gelu_flag) {
                    float c0 = v0 + 0.044715f * v0 * v0 * v0;
                    v0 = 0.5f * v0 * (1.f + tanhf(0.7978845608028654f * c0));
                    float c1 = v1 + 0.044715f * v1 * v1 * v1;
                    v1 = 0.5f * v1 * (1.f + tanhf(0.7978845608028654f * c1));
                }
                *(float2*)&OutZ[(size_t)tok[q] * Nout + col] = make_float2(v0, v1);
            }
        }
    }
}

// ============ flash attention: m16n8k8 tf32 MMA, BQ=64, BK=64 (unchanged) ============
#define ASTR 68
#define ATT2_SMEM_WORDS (4 * 64 * ASTR + 128 + 128 + 64)

__global__ void __launch_bounds__(256)
attn_mma(const float* __restrict__ qkv, const unsigned char* __restrict__ mask,
         float* __restrict__ ctx) {
    extern __shared__ uint32_t sm4[];
    uint32_t* Qs = sm4;
    uint32_t* Ks = Qs + 64 * ASTR;
    uint32_t* Vt = Ks + 64 * ASTR;
    uint32_t* Ps = Vt + 64 * ASTR;
    float* redm  = (float*)(Ps + 64 * ASTR);
    float* redl  = redm + 128;
    float* maskS = redl + 128;

    int bh = blockIdx.y;
    int b = bh >> 4, h = bh & 15;
    int n0 = blockIdx.x << 6;
    int tid = threadIdx.x, lane = tid & 31, wid = tid >> 5;
    int g = lane >> 2, tg = lane & 3;
    int warp_m = wid & 3, warp_n = wid >> 2;
    int row0 = warp_m * 16 + g, row1 = row0 + 8;

    int lrow = tid & 63, d0 = (tid >> 6) << 4;

    {
        const float* qp = qkv + (size_t)(b * 1024 + n0 + lrow) * 3072 + h * 64 + d0;
        #pragma unroll
        for (int i = 0; i < 16; i += 4) {
            float4 v = *(const float4*)(qp + i);
            *(uint4*)&Qs[lrow * ASTR + d0 + i] =
                make_uint4(f2tf32(v.x), f2tf32(v.y), f2tf32(v.z), f2tf32(v.w));
        }
    }

    float o[4][4];
    #pragma unroll
    for (int ni = 0; ni < 4; ni++)
        #pragma unroll
        for (int q = 0; q < 4; q++) o[ni][q] = 0.f;
    float m0 = -1e30f, m1 = -1e30f, l0 = 0.f, l1 = 0.f;

    for (int kt = 0; kt < 16; kt++) {
        {
            const float* base = qkv + (size_t)(b * 1024 + kt * 64 + lrow) * 3072 + h * 64 + d0;
            #pragma unroll
            for (int i = 0; i < 16; i += 4) {
                float4 kv = *(const float4*)(base + 1024 + i);
                *(uint4*)&Ks[lrow * ASTR + d0 + i] =
                    make_uint4(f2tf32(kv.x), f2tf32(kv.y), f2tf32(kv.z), f2tf32(kv.w));
            }
            #pragma unroll
            for (int i = 0; i < 16; i += 4) {
                float4 vv = *(const float4*)(base + 2048 + i);
                Vt[(d0 + i + 0) * ASTR + lrow] = f2tf32(vv.x);
                Vt[(d0 + i + 1) * ASTR + lrow] = f2tf32(vv.y);
                Vt[(d0 + i + 2) * ASTR + lrow] = f2tf32(vv.z);
                Vt[(d0 + i + 3) * ASTR + lrow] = f2tf32(vv.w);
            }
            if (tid < 64)
                maskS[tid] = mask[b * 1024 + kt * 64 + tid] ? -10000.f : 0.f;
        }
        __syncthreads();

        float s[4][4];
        #pragma unroll
        for (int ni = 0; ni < 4; ni++)
            #pragma unroll
            for (int q = 0; q < 4; q++) s[ni][q] = 0.f;
        #pragma unroll
        for (int kb = 0; kb < 64; kb += 8) {
            uint32_t a0 = Qs[row0 * ASTR + kb + tg];
            uint32_t a1 = Qs[row1 * ASTR + kb + tg];
            uint32_t a2 = Qs[row0 * ASTR + kb + tg + 4];
            uint32_t a3 = Qs[row1 * ASTR + kb + tg + 4];
            #pragma unroll
            for (int ni = 0; ni < 4; ni++) {
                int n = warp_n * 32 + ni * 8 + g;
                uint32_t b0 = Ks[n * ASTR + kb + tg];
                uint32_t b1 = Ks[n * ASTR + kb + tg + 4];
                mma_tf32(s[ni][0], s[ni][1], s[ni][2], s[ni][3], a0, a1, a2, a3, b0, b1);
            }
        }
        #pragma unroll
        for (int ni = 0; ni < 4; ni++) {
            int c0 = warp_n * 32 + ni * 8 + 2 * tg;
            float mv0 = maskS[c0], mv1 = maskS[c0 + 1];
            s[ni][0] = s[ni][0] * 0.125f + mv0;
            s[ni][1] = s[ni][1] * 0.125f + mv1;
            s[ni][2] = s[ni][2] * 0.125f + mv0;
            s[ni][3] = s[ni][3] * 0.125f + mv1;
        }

        float rm0 = -1e30f, rm1 = -1e30f;
        #pragma unroll
        for (int ni = 0; ni < 4; ni++) {
            rm0 = fmaxf(rm0, fmaxf(s[ni][0], s[ni][1]));
            rm1 = fmaxf(rm1, fmaxf(s[ni][2], s[ni][3]));
        }
        rm0 = fmaxf(rm0, __shfl_xor_sync(0xffffffffu, rm0, 1));
        rm0 = fmaxf(rm0, __shfl_xor_sync(0xffffffffu, rm0, 2));
        rm1 = fmaxf(rm1, __shfl_xor_sync(0xffffffffu, rm1, 1));
        rm1 = fmaxf(rm1, __shfl_xor_sync(0xffffffffu, rm1, 2));
        if (tg == 0) {
            redm[warp_n * 64 + row0] = rm0;
            redm[warp_n * 64 + row1] = rm1;
        }
        __syncthreads();
        float mn0 = fmaxf(m0, fmaxf(redm[row0], redm[64 + row0]));
        float mn1 = fmaxf(m1, fmaxf(redm[row1], redm[64 + row1]));
        float sc0 = __expf(m0 - mn0), sc1 = __expf(m1 - mn1);
        m0 = mn0; m1 = mn1;

        float ps0 = 0.f, ps1 = 0.f;
        #pragma unroll
        for (int ni = 0; ni < 4; ni++) {
            int c0 = warp_n * 32 + ni * 8 + 2 * tg;
            s[ni][0] = __expf(s[ni][0] - mn0);
            s[ni][1] = __expf(s[ni][1] - mn0);
            s[ni][2] = __expf(s[ni][2] - mn1);
            s[ni][3] = __expf(s[ni][3] - mn1);
            ps0 += s[ni][0] + s[ni][1];
            ps1 += s[ni][2] + s[ni][3];
            Ps[row0 * ASTR + c0]     = f2tf32(s[ni][0]);
            Ps[row0 * ASTR + c0 + 1] = f2tf32(s[ni][1]);
            Ps[row1 * ASTR + c0]     = f2tf32(s[ni][2]);
            Ps[row1 * ASTR + c0 + 1] = f2tf32(s[ni][3]);
        }
        ps0 += __shfl_xor_sync(0xffffffffu, ps0, 1);
        ps0 += __shfl_xor_sync(0xffffffffu, ps0, 2);
        ps1 += __shfl_xor_sync(0xffffffffu, ps1, 1);
        ps1 += __shfl_xor_sync(0xffffffffu, ps1, 2);
        if (tg == 0) {
            redl[warp_n * 64 + row0] = ps0;
            redl[warp_n * 64 + row1] = ps1;
        }
        #pragma unroll
        for (int ni = 0; ni < 4; ni++) {
            o[ni][0] *= sc0; o[ni][1] *= sc0;
            o[ni][2] *= sc1; o[ni][3] *= sc1;
        }
        __syncthreads();
        l0 = l0 * sc0 + redl[row0] + redl[64 + row0];
        l1 = l1 * sc1 + redl[row1] + redl[64 + row1];

        #pragma unroll
        for (int kb = 0; kb < 64; kb += 8) {
            uint32_t a0 = Ps[row0 * ASTR + kb + tg];
            uint32_t a1 = Ps[row1 * ASTR + kb + tg];
            uint32_t a2 = Ps[row0 * ASTR + kb + tg + 4];
            uint32_t a3 = Ps[row1 * ASTR + kb + tg + 4];
            #pragma unroll
            for (int ni = 0; ni < 4; ni++) {
                int n = warp_n * 32 + ni * 8 + g;
                uint32_t b0 = Vt[n * ASTR + kb + tg];
                uint32_t b1 = Vt[n * ASTR + kb + tg + 4];
                mma_tf32(o[ni][0], o[ni][1], o[ni][2], o[ni][3], a0, a1, a2, a3, b0, b1);
            }
        }
        __syncthreads();
    }

    float inv0 = 1.f / l0, inv1 = 1.f / l1;
    int t0 = b * 1024 + n0 + row0;
    int t1 = b * 1024 + n0 + row1;
    #pragma unroll
    for (int ni = 0; ni < 4; ni++) {
        int c = warp_n * 32 + ni * 8 + 2 * tg;
        *(float2*)&ctx[(size_t)t0 * 1024 + h * 64 + c] =
            make_float2(o[ni][0] * inv0, o[ni][1] * inv0);
        *(float2*)&ctx[(size_t)t1 * 1024 + h * 64 + c] =
            make_float2(o[ni][2] * inv1, o[ni][3] * inv1);
    }
}

// ---------------- residual + layernorm over a + sum of nb partials ----------------
__global__ void __launch_bounds__(256)
ln_kernel(const float* __restrict__ a, const float* __restrict__ p0,
          const float* __restrict__ p1, const float* __restrict__ p2,
          const float* __restrict__ p3, int nb,
          const float* __restrict__ s, const float* __restrict__ bias,
          float* __restrict__ out) {
    int t = blockIdx.x;
    int base = threadIdx.x << 2;
    size_t off = (size_t)t * DM + base;
    float4 av = *(const float4*)(a + off);
    float4 bv = *(const float4*)(p0 + off);
    float v[4] = {av.x + bv.x, av.y + bv.y, av.z + bv.z, av.w + bv.w};
    if (nb > 1) {
        float4 c = *(const float4*)(p1 + off);
        v[0] += c.x; v[1] += c.y; v[2] += c.z; v[3] += c.w;
    }
    if (nb > 2) {
        float4 c = *(const float4*)(p2 + off);
        v[0] += c.x; v[1] += c.y; v[2] += c.z; v[3] += c.w;
        float4 d = *(const float4*)(p3 + off);
        v[0] += d.x; v[1] += d.y; v[2] += d.z; v[3] += d.w;
    }
    float s1 = v[0] + v[1] + v[2] + v[3];
    float s2 = v[0] * v[0] + v[1] * v[1] + v[2] * v[2] + v[3] * v[3];
    #pragma unroll
    for (int o = 16; o; o >>= 1) {
        s1 += __shfl_xor_sync(0xffffffffu, s1, o);
        s2 += __shfl_xor_sync(0xffffffffu, s2, o);
    }
    __shared__ float w1[8], w2[8];
    __shared__ float sh_mean, sh_inv;
    int warp = threadIdx.x >> 5, lane = threadIdx.x & 31;
    if (lane == 0) { w1[warp] = s1; w2[warp] = s2; }
    __syncthreads();
    if (threadIdx.x == 0) {
        float A = 0.f, B = 0.f;
        #pragma unroll
        for (int i = 0; i < 8; i++) { A += w1[i]; B += w2[i]; }
        float mean = A * (1.f / DM);
        float var = B * (1.f / DM) - mean * mean;
        sh_mean = mean;
        sh_inv = rsqrtf(var + 1e-5f);
    }
    __syncthreads();
    float mean = sh_mean, inv = sh_inv;
    float4 sv = *(const float4*)(s + base);
    float4 biv = *(const float4*)(bias + base);
    float4 ov;
    ov.x = (v[0] - mean) * inv * sv.x + biv.x;
    ov.y = (v[1] - mean) * inv * sv.y + biv.y;
    ov.z = (v[2] - mean) * inv * sv.z + biv.z;
    ov.w = (v[3] - mean) * inv * sv.w + biv.w;
    *(float4*)(out + off) = ov;
}

// ---------------- launch ----------------
extern "C" void kernel_launch(void* const* d_in, const int* in_sizes, int n_in,
                              void* d_out, int out_size) {
    const float* src     = (const float*)d_in[0];
    const unsigned char* mask = (const unsigned char*)d_in[1];
    const float* Wg_attn = (const float*)d_in[2];
    const float* Wqkv    = (const float*)d_in[3];
    const float* bqkv    = (const float*)d_in[4];
    const float* Wo      = (const float*)d_in[5];
    const float* bo      = (const float*)d_in[6];
    const float* Wg_ffn  = (const float*)d_in[7];
    const float* W1      = (const float*)d_in[8];
    const float* b1      = (const float*)d_in[9];
    const float* W2      = (const float*)d_in[10];
    const float* b2      = (const float*)d_in[11];
    const float* ln1_s   = (const float*)d_in[12];
    const float* ln1_b   = (const float*)d_in[13];
    const float* ln2_s   = (const float*)d_in[14];
    const float* ln2_b   = (const float*)d_in[15];
    float* out = (float*)d_out;

    float *qkv, *ctx, *x, *tmp, *hbuf, *gw0, *gw1;
    int *idx0, *idx1, *perm0, *perm1, *te0, *te1;
    cudaGetSymbolAddress((void**)&qkv,  g_qkv);
    cudaGetSymbolAddress((void**)&ctx,  g_ctx);
    cudaGetSymbolAddress((void**)&x,    g_x);
    cudaGetSymbolAddress((void**)&tmp,  g_tmp);
    cudaGetSymbolAddress((void**)&hbuf, g_h);
    cudaGetSymbolAddress((void**)&gw0,  g_gw0);
    cudaGetSymbolAddress((void**)&gw1,  g_gw1);
    cudaGetSymbolAddress((void**)&idx0, g_idx0);
    cudaGetSymbolAddress((void**)&idx1, g_idx1);
    cudaGetSymbolAddress((void**)&perm0, g_perm0);
    cudaGetSymbolAddress((void**)&perm1, g_perm1);
    cudaGetSymbolAddress((void**)&te0,  g_te0);
    cudaGetSymbolAddress((void**)&te1,  g_te1);

    float* tmp1 = tmp + (size_t)TKN * DM;
    float* tmp2 = tmp + (size_t)2 * TKN * DM;
    float* tmp3 = tmp + (size_t)3 * TKN * DM;

    int att_smem = ATT2_SMEM_WORDS * (int)sizeof(uint32_t);
    cudaFuncSetAttribute(attn_mma, cudaFuncAttributeMaxDynamicSharedMemorySize, att_smem);

    // 1. attention gate + grouping
    gate_kernel<<<TKN, 256>>>(src, Wg_attn, idx0, gw0);
    scatter_kernel<<<1, 256>>>(idx0, perm0, te0);
    // 2. QKV projection (tf32 mma)
    moe_gemm_mma<<<dim3(3 * DM / 128, MAXTILES, 1), 256>>>(
        src, Wqkv, bqkv, gw0, perm0, te0, qkv, DM, 3 * DM, 0, DM);
    // 3. attention (tf32 mma)
    attn_mma<<<dim3(1024 / 64, 2 * NH), 256, att_smem>>>(qkv, mask, ctx);
    // 4. output projection, split-K x2
    moe_gemm_mma<<<dim3(DM / 128, MAXTILES, 2), 256>>>(
        ctx, Wo, bo, gw0, perm0, te0, tmp, DM, DM, 0, DM / 2);
    // 5. x = LN1(src + tmp0 + tmp1)
    ln_kernel<<<TKN, 256>>>(src, tmp, tmp1, tmp1, tmp1, 2, ln1_s, ln1_b, x);
    // 6. ffn gate + grouping
    gate_kernel<<<TKN, 256>>>(x, Wg_ffn, idx1, gw1);
    scatter_kernel<<<1, 256>>>(idx1, perm1, te1);
    // 7. h = gelu(gated W1) (no split: gelu is nonlinear)
    moe_gemm_mma<<<dim3(FFD / 128, MAXTILES, 1), 256>>>(
        x, W1, b1, gw1, perm1, te1, hbuf, DM, FFD, 1, DM);
    // 8. ffn = gated W2, split-K x4
    moe_gemm_mma<<<dim3(DM / 128, MAXTILES, 4), 256>>>(
        hbuf, W2, b2, gw1, perm1, te1, tmp, FFD, DM, 0, FFD / 4);
    // 9. out = LN2(x + tmp0..3)
    ln_kernel<<<TKN, 256>>>(x, tmp, tmp1, tmp2, tmp3, 4, ln2_s, ln2_b, out);
}

// round 9
// speedup vs baseline: 1.4011x; 1.0823x over previous
#include <cuda_runtime.h>
#include <math.h>
#include <stdint.h>

// Problem constants
#define TKN 2048          // B*N tokens
#define DM 1024           // model dim
#define NE 8              // experts
#define FFD 4096          // ffn dim
#define NH 16             // heads
#define HD 64             // head dim
#define PADROWS 3072      // token rows padded to 128 per expert segment
#define MAXTILES 24       // PADROWS/128

// ---------------- scratch (device globals; no allocation allowed) ----------------
__device__ float g_qkv[TKN * 3 * DM];
__device__ float g_ctx[TKN * DM];
__device__ float g_x[TKN * DM];
__device__ float g_tmp[8 * TKN * DM];     // up to 8 split-K partials
__device__ float g_h[TKN * FFD];
__device__ int   g_idx0[TKN];
__device__ int   g_idx1[TKN];
__device__ float g_gw0[TKN];
__device__ float g_gw1[TKN];
__device__ int   g_perm0[PADROWS];
__device__ int   g_perm1[PADROWS];
__device__ int   g_te0[MAXTILES];
__device__ int   g_te1[MAXTILES];

__device__ __forceinline__ uint32_t f2tf32(float x) {
    uint32_t r;
    asm("cvt.rna.tf32.f32 %0, %1;" : "=r"(r) : "f"(x));
    return r;
}
__device__ __forceinline__ void mma_tf32(float& c0, float& c1, float& c2, float& c3,
                                         uint32_t a0, uint32_t a1, uint32_t a2, uint32_t a3,
                                         uint32_t b0, uint32_t b1) {
    asm volatile(
        "mma.sync.aligned.m16n8k8.row.col.f32.tf32.tf32.f32 "
        "{%0,%1,%2,%3}, {%4,%5,%6,%7}, {%8,%9}, {%0,%1,%2,%3};"
        : "+f"(c0), "+f"(c1), "+f"(c2), "+f"(c3)
        : "r"(a0), "r"(a1), "r"(a2), "r"(a3), "r"(b0), "r"(b1));
}

// ---------------- gate ----------------
__global__ void gate_kernel(const float* __restrict__ x, const float* __restrict__ Wg,
                            int* __restrict__ idx, float* __restrict__ gw) {
    int t = blockIdx.x;
    int warp = threadIdx.x >> 5, lane = threadIdx.x & 31;
    const float* xr = x + (size_t)t * DM;
    float s = 0.f;
    #pragma unroll 4
    for (int d = lane; d < DM; d += 32) s += xr[d] * Wg[d * NE + warp];
    #pragma unroll
    for (int o = 16; o; o >>= 1) s += __shfl_xor_sync(0xffffffffu, s, o);
    __shared__ float logits[NE];
    if (lane == 0) logits[warp] = s;
    __syncthreads();
    if (threadIdx.x == 0) {
        float best = logits[0]; int bi = 0;
        #pragma unroll
        for (int e = 1; e < NE; e++) if (logits[e] > best) { best = logits[e]; bi = e; }
        float sum = 0.f;
        #pragma unroll
        for (int e = 0; e < NE; e++) sum += expf(logits[e] - best);
        idx[t] = bi;
        gw[t] = 1.f / sum;
    }
}

// ---------------- scatter ----------------
__global__ void scatter_kernel(const int* __restrict__ idx, int* __restrict__ perm,
                               int* __restrict__ tile_expert) {
    __shared__ int cnt[NE];
    __shared__ int cur[NE];
    int tid = threadIdx.x;
    if (tid < NE) cnt[tid] = 0;
    for (int i = tid; i < PADROWS; i += blockDim.x) perm[i] = -1;
    __syncthreads();
    for (int t = tid; t < TKN; t += blockDim.x) atomicAdd(&cnt[idx[t]], 1);
    __syncthreads();
    if (tid == 0) {
        int c = 0;
        for (int e = 0; e < NE; e++) {
            cur[e] = c;
            int tiles = (cnt[e] + 127) >> 7;
            for (int i = 0; i < tiles; i++) tile_expert[(c >> 7) + i] = e;
            c += tiles << 7;
        }
        for (int i = c >> 7; i < MAXTILES; i++) tile_expert[i] = -1;
    }
    __syncthreads();
    for (int t = tid; t < TKN; t += blockDim.x) {
        int p = atomicAdd(&cur[idx[t]], 1);
        perm[p] = t;
    }
}

// ============ tf32 mma.sync MoE GEMM with split-K (R8 proven) ============
#define KSTRIDE 136
#define STGW (16 * KSTRIDE)

__global__ void __launch_bounds__(256, 2)
moe_gemm_mma(const float* __restrict__ In, const float* __restrict__ W,
             const float* __restrict__ bias, const float* __restrict__ gw,
             const int* __restrict__ perm, const int* __restrict__ tile_expert,
             float* __restrict__ Out, int Ktot, int Nout, int gelu_flag, int klen) {
    int e = tile_expert[blockIdx.y];
    if (e < 0) return;
    __shared__ uint32_t SA[2][STGW];
    __shared__ uint32_t SB[2][STGW];

    int tid = threadIdx.x, wid = tid >> 5, lane = tid & 31;
    int g = lane >> 2, tg = lane & 3;
    int warp_m = wid & 3, warp_n = wid >> 2;
    int row0 = blockIdx.y << 7, col0 = blockIdx.x << 7;
    int k0off = blockIdx.z * klen;
    float* OutZ = Out + (size_t)blockIdx.z * TKN * Nout;
    float bsel = (blockIdx.z == 0) ? 1.f : 0.f;

    int mS = tid & 127;
    int kqS = (tid >> 7) << 3;
    int tokA = perm[row0 + mS];
    const float* aptr = (tokA >= 0) ? (In + (size_t)tokA * Ktot + k0off + kqS) : In;
    int k2 = (tid >> 5) << 1;
    int nB4 = (tid & 31) << 2;
    const float* bptr = W + ((size_t)e * Ktot + k0off + k2) * Nout + col0 + nB4;

    float acc[2][8][4];
    #pragma unroll
    for (int mi = 0; mi < 2; mi++)
        #pragma unroll
        for (int ni = 0; ni < 8; ni++)
            #pragma unroll
            for (int q = 0; q < 4; q++) acc[mi][ni][q] = 0.f;

    int nchunk = klen >> 4;

    {
        float4 av0 = make_float4(0.f,0.f,0.f,0.f), av1 = av0;
        if (tokA >= 0) { av0 = *(const float4*)(aptr); av1 = *(const float4*)(aptr + 4); }
        float4 bv0 = *(const float4*)(bptr);
        float4 bv1 = *(const float4*)(bptr + Nout);
        SA[0][(kqS + 0) * KSTRIDE + mS] = f2tf32(av0.x);
        SA[0][(kqS + 1) * KSTRIDE + mS] = f2tf32(av0.y);
        SA[0][(kqS + 2) * KSTRIDE + mS] = f2tf32(av0.z);
        SA[0][(kqS + 3) * KSTRIDE + mS] = f2tf32(av0.w);
        SA[0][(kqS + 4) * KSTRIDE + mS] = f2tf32(av1.x);
        SA[0][(kqS + 5) * KSTRIDE + mS] = f2tf32(av1.y);
        SA[0][(kqS + 6) * KSTRIDE + mS] = f2tf32(av1.z);
        SA[0][(kqS + 7) * KSTRIDE + mS] = f2tf32(av1.w);
        *(uint4*)&SB[0][k2 * KSTRIDE + nB4] =
            make_uint4(f2tf32(bv0.x), f2tf32(bv0.y), f2tf32(bv0.z), f2tf32(bv0.w));
        *(uint4*)&SB[0][(k2 + 1) * KSTRIDE + nB4] =
            make_uint4(f2tf32(bv1.x), f2tf32(bv1.y), f2tf32(bv1.z), f2tf32(bv1.w));
    }
    __syncthreads();

    int am0 = warp_m * 32 + g;
    int bn0 = warp_n * 64 + g;

    for (int c = 0; c < nchunk; c++) {
        int buf = c & 1;
        bool has_next = (c + 1) < nchunk;
        float4 av0, av1, bv0, bv1;
        if (has_next) {
            int k0 = (c + 1) << 4;
            if (tokA >= 0) {
                av0 = *(const float4*)(aptr + k0);
                av1 = *(const float4*)(aptr + k0 + 4);
            } else { av0 = make_float4(0.f,0.f,0.f,0.f); av1 = av0; }
            const float* bp = bptr + (size_t)k0 * Nout;
            bv0 = *(const float4*)(bp);
            bv1 = *(const float4*)(bp + Nout);
        }

        const uint32_t* Ab = SA[buf];
        const uint32_t* Bb = SB[buf];
        #pragma unroll
        for (int ks = 0; ks < 2; ks++) {
            int kb = ks << 3;
            uint32_t a[2][4];
            #pragma unroll
            for (int mi = 0; mi < 2; mi++) {
                int m = am0 + mi * 16;
                a[mi][0] = Ab[(kb + tg) * KSTRIDE + m];
                a[mi][1] = Ab[(kb + tg) * KSTRIDE + m + 8];
                a[mi][2] = Ab[(kb + tg + 4) * KSTRIDE + m];
                a[mi][3] = Ab[(kb + tg + 4) * KSTRIDE + m + 8];
            }
            #pragma unroll
            for (int ni = 0; ni < 8; ni++) {
                int n = bn0 + ni * 8;
                uint32_t b0 = Bb[(kb + tg) * KSTRIDE + n];
                uint32_t b1 = Bb[(kb + tg + 4) * KSTRIDE + n];
                mma_tf32(acc[0][ni][0], acc[0][ni][1], acc[0][ni][2], acc[0][ni][3],
                         a[0][0], a[0][1], a[0][2], a[0][3], b0, b1);
                mma_tf32(acc[1][ni][0], acc[1][ni][1], acc[1][ni][2], acc[1][ni][3],
                         a[1][0], a[1][1], a[1][2], a[1][3], b0, b1);
            }
        }

        if (has_next) {
            int nb = buf ^ 1;
            SA[nb][(kqS + 0) * KSTRIDE + mS] = f2tf32(av0.x);
            SA[nb][(kqS + 1) * KSTRIDE + mS] = f2tf32(av0.y);
            SA[nb][(kqS + 2) * KSTRIDE + mS] = f2tf32(av0.z);
            SA[nb][(kqS + 3) * KSTRIDE + mS] = f2tf32(av0.w);
            SA[nb][(kqS + 4) * KSTRIDE + mS] = f2tf32(av1.x);
            SA[nb][(kqS + 5) * KSTRIDE + mS] = f2tf32(av1.y);
            SA[nb][(kqS + 6) * KSTRIDE + mS] = f2tf32(av1.z);
            SA[nb][(kqS + 7) * KSTRIDE + mS] = f2tf32(av1.w);
            *(uint4*)&SB[nb][k2 * KSTRIDE + nB4] =
                make_uint4(f2tf32(bv0.x), f2tf32(bv0.y), f2tf32(bv0.z), f2tf32(bv0.w));
            *(uint4*)&SB[nb][(k2 + 1) * KSTRIDE + nB4] =
                make_uint4(f2tf32(bv1.x), f2tf32(bv1.y), f2tf32(bv1.z), f2tf32(bv1.w));
            __syncthreads();
        }
    }

    int tok[4]; float gwv[4];
    #pragma unroll
    for (int q = 0; q < 4; q++) {
        int r = row0 + warp_m * 32 + g + q * 8;
        tok[q] = perm[r];
        gwv[q] = (tok[q] >= 0) ? gw[tok[q]] : 0.f;
    }
    #pragma unroll
    for (int ni = 0; ni < 8; ni++) {
        int col = col0 + warp_n * 64 + ni * 8 + 2 * tg;
        float2 bs2 = *(const float2*)&bias[(size_t)e * Nout + col];
        bs2.x *= bsel; bs2.y *= bsel;
        #pragma unroll
        for (int mi = 0; mi < 2; mi++) {
            #pragma unroll
            for (int half = 0; half < 2; half++) {
                int q = mi * 2 + half;
                if (tok[q] < 0) continue;
                float v0 = (acc[mi][ni][half * 2 + 0] + bs2.x) * gwv[q];
                float v1 = (acc[mi][ni][half * 2 + 1] + bs2.y) * gwv[q];
                if (gelu_flag) {
                    float c0 = v0 + 0.044715f * v0 * v0 * v0;
                    v0 = 0.5f * v0 * (1.f + tanhf(0.7978845608028654f * c0));
                    float c1 = v1 + 0.044715f * v1 * v1 * v1;
                    v1 = 0.5f * v1 * (1.f + tanhf(0.7978845608028654f * c1));
                }
                *(float2*)&OutZ[(size_t)tok[q] * Nout + col] = make_float2(v0, v1);
            }
        }
    }
}

// ============ flash attention: BQ=128, BK=64, tf32 mma, 8 warps (4M x 2N) ============
// Warp tile: S 32x32, O 32x32. Same fragment pattern as GEMM (mi stride 16).
#define ASTR 68
#define ATT3_SMEM_WORDS ((128 + 64 + 64 + 128) * ASTR + 256 + 256 + 64)

__global__ void __launch_bounds__(256, 2)
attn_mma(const float* __restrict__ qkv, const unsigned char* __restrict__ mask,
         float* __restrict__ ctx) {
    extern __shared__ uint32_t sm4[];
    uint32_t* Qs = sm4;                     // [128][68]
    uint32_t* Ks = Qs + 128 * ASTR;         // [64][68] key-major
    uint32_t* Vt = Ks + 64 * ASTR;          // [64][68] d-major
    uint32_t* Ps = Vt + 64 * ASTR;          // [128][68]
    float* redm  = (float*)(Ps + 128 * ASTR);  // [2][128]
    float* redl  = redm + 256;                 // [2][128]
    float* maskS = redl + 256;                 // [64]

    int bh = blockIdx.y;
    int b = bh >> 4, h = bh & 15;
    int n0 = blockIdx.x << 7;
    int tid = threadIdx.x, lane = tid & 31, wid = tid >> 5;
    int g = lane >> 2, tg = lane & 3;
    int warp_m = wid & 3, warp_n = wid >> 2;
    int am0 = warp_m * 32 + g;

    // ---- load Q tile (128x64) ----
    {
        int qrow = tid & 127, qd0 = (tid >> 7) << 5;
        const float* qp = qkv + (size_t)(b * 1024 + n0 + qrow) * 3072 + h * 64 + qd0;
        #pragma unroll
        for (int i = 0; i < 32; i += 4) {
            float4 v = *(const float4*)(qp + i);
            *(uint4*)&Qs[qrow * ASTR + qd0 + i] =
                make_uint4(f2tf32(v.x), f2tf32(v.y), f2tf32(v.z), f2tf32(v.w));
        }
    }

    float o[2][4][4];
    float m[2][2], l[2][2];
    #pragma unroll
    for (int mi = 0; mi < 2; mi++) {
        m[mi][0] = m[mi][1] = -1e30f;
        l[mi][0] = l[mi][1] = 0.f;
        #pragma unroll
        for (int ni = 0; ni < 4; ni++)
            #pragma unroll
            for (int q = 0; q < 4; q++) o[mi][ni][q] = 0.f;
    }

    int lrow = tid & 63, d0 = (tid >> 6) << 4;

    for (int kt = 0; kt < 16; kt++) {
        // ---- load K (key-major) + V (d-major transpose) ----
        {
            const float* base = qkv + (size_t)(b * 1024 + kt * 64 + lrow) * 3072 + h * 64 + d0;
            #pragma unroll
            for (int i = 0; i < 16; i += 4) {
                float4 kv = *(const float4*)(base + 1024 + i);
                *(uint4*)&Ks[lrow * ASTR + d0 + i] =
                    make_uint4(f2tf32(kv.x), f2tf32(kv.y), f2tf32(kv.z), f2tf32(kv.w));
            }
            #pragma unroll
            for (int i = 0; i < 16; i += 4) {
                float4 vv = *(const float4*)(base + 2048 + i);
                Vt[(d0 + i + 0) * ASTR + lrow] = f2tf32(vv.x);
                Vt[(d0 + i + 1) * ASTR + lrow] = f2tf32(vv.y);
                Vt[(d0 + i + 2) * ASTR + lrow] = f2tf32(vv.z);
                Vt[(d0 + i + 3) * ASTR + lrow] = f2tf32(vv.w);
            }
            if (tid < 64)
                maskS[tid] = mask[b * 1024 + kt * 64 + tid] ? -10000.f : 0.f;
        }
        __syncthreads();

        // ---- S = Q K^T ----
        float s[2][4][4];
        #pragma unroll
        for (int mi = 0; mi < 2; mi++)
            #pragma unroll
            for (int ni = 0; ni < 4; ni++)
                #pragma unroll
                for (int q = 0; q < 4; q++) s[mi][ni][q] = 0.f;
        #pragma unroll
        for (int kb = 0; kb < 64; kb += 8) {
            uint32_t a[2][4];
            #pragma unroll
            for (int mi = 0; mi < 2; mi++) {
                int r = am0 + mi * 16;
                a[mi][0] = Qs[r * ASTR + kb + tg];
                a[mi][1] = Qs[(r + 8) * ASTR + kb + tg];
                a[mi][2] = Qs[r * ASTR + kb + tg + 4];
                a[mi][3] = Qs[(r + 8) * ASTR + kb + tg + 4];
            }
            #pragma unroll
            for (int ni = 0; ni < 4; ni++) {
                int n = warp_n * 32 + ni * 8 + g;
                uint32_t b0 = Ks[n * ASTR + kb + tg];
                uint32_t b1 = Ks[n * ASTR + kb + tg + 4];
                mma_tf32(s[0][ni][0], s[0][ni][1], s[0][ni][2], s[0][ni][3],
                         a[0][0], a[0][1], a[0][2], a[0][3], b0, b1);
                mma_tf32(s[1][ni][0], s[1][ni][1], s[1][ni][2], s[1][ni][3],
                         a[1][0], a[1][1], a[1][2], a[1][3], b0, b1);
            }
        }
        // ---- scale + mask ----
        #pragma unroll
        for (int ni = 0; ni < 4; ni++) {
            int c0 = warp_n * 32 + ni * 8 + 2 * tg;
            float mv0 = maskS[c0], mv1 = maskS[c0 + 1];
            #pragma unroll
            for (int mi = 0; mi < 2; mi++) {
                s[mi][ni][0] = s[mi][ni][0] * 0.125f + mv0;
                s[mi][ni][1] = s[mi][ni][1] * 0.125f + mv1;
                s[mi][ni][2] = s[mi][ni][2] * 0.125f + mv0;
                s[mi][ni][3] = s[mi][ni][3] * 0.125f + mv1;
            }
        }

        // ---- row max ----
        float mn[2][2], sc[2][2];
        #pragma unroll
        for (int mi = 0; mi < 2; mi++) {
            float rm0 = -1e30f, rm1 = -1e30f;
            #pragma unroll
            for (int ni = 0; ni < 4; ni++) {
                rm0 = fmaxf(rm0, fmaxf(s[mi][ni][0], s[mi][ni][1]));
                rm1 = fmaxf(rm1, fmaxf(s[mi][ni][2], s[mi][ni][3]));
            }
            rm0 = fmaxf(rm0, __shfl_xor_sync(0xffffffffu, rm0, 1));
            rm0 = fmaxf(rm0, __shfl_xor_sync(0xffffffffu, rm0, 2));
            rm1 = fmaxf(rm1, __shfl_xor_sync(0xffffffffu, rm1, 1));
            rm1 = fmaxf(rm1, __shfl_xor_sync(0xffffffffu, rm1, 2));
            if (tg == 0) {
                int r = am0 + mi * 16;
                redm[warp_n * 128 + r] = rm0;
                redm[warp_n * 128 + r + 8] = rm1;
            }
        }
        __syncthreads();
        #pragma unroll
        for (int mi = 0; mi < 2; mi++) {
            int r = am0 + mi * 16;
            mn[mi][0] = fmaxf(m[mi][0], fmaxf(redm[r], redm[128 + r]));
            mn[mi][1] = fmaxf(m[mi][1], fmaxf(redm[r + 8], redm[128 + r + 8]));
            sc[mi][0] = __expf(m[mi][0] - mn[mi][0]);
            sc[mi][1] = __expf(m[mi][1] - mn[mi][1]);
            m[mi][0] = mn[mi][0]; m[mi][1] = mn[mi][1];
        }

        // ---- p = exp(s-m), write Ps, partial sums ----
        #pragma unroll
        for (int mi = 0; mi < 2; mi++) {
            int r = am0 + mi * 16;
            float ps0 = 0.f, ps1 = 0.f;
            #pragma unroll
            for (int ni = 0; ni < 4; ni++) {
                int c0 = warp_n * 32 + ni * 8 + 2 * tg;
                s[mi][ni][0] = __expf(s[mi][ni][0] - mn[mi][0]);
                s[mi][ni][1] = __expf(s[mi][ni][1] - mn[mi][0]);
                s[mi][ni][2] = __expf(s[mi][ni][2] - mn[mi][1]);
                s[mi][ni][3] = __expf(s[mi][ni][3] - mn[mi][1]);
                ps0 += s[mi][ni][0] + s[mi][ni][1];
                ps1 += s[mi][ni][2] + s[mi][ni][3];
                Ps[r * ASTR + c0]           = f2tf32(s[mi][ni][0]);
                Ps[r * ASTR + c0 + 1]       = f2tf32(s[mi][ni][1]);
                Ps[(r + 8) * ASTR + c0]     = f2tf32(s[mi][ni][2]);
                Ps[(r + 8) * ASTR + c0 + 1] = f2tf32(s[mi][ni][3]);
            }
            ps0 += __shfl_xor_sync(0xffffffffu, ps0, 1);
            ps0 += __shfl_xor_sync(0xffffffffu, ps0, 2);
            ps1 += __shfl_xor_sync(0xffffffffu, ps1, 1);
            ps1 += __shfl_xor_sync(0xffffffffu, ps1, 2);
            if (tg == 0) {
                redl[warp_n * 128 + r] = ps0;
                redl[warp_n * 128 + r + 8] = ps1;
            }
            // rescale O
            #pragma unroll
            for (int ni = 0; ni < 4; ni++) {
                o[mi][ni][0] *= sc[mi][0]; o[mi][ni][1] *= sc[mi][0];
                o[mi][ni][2] *= sc[mi][1]; o[mi][ni][3] *= sc[mi][1];
            }
        }
        __syncthreads();
        #pragma unroll
        for (int mi = 0; mi < 2; mi++) {
            int r = am0 + mi * 16;
            l[mi][0] = l[mi][0] * sc[mi][0] + redl[r] + redl[128 + r];
            l[mi][1] = l[mi][1] * sc[mi][1] + redl[r + 8] + redl[128 + r + 8];
        }

        // ---- O += P V ----
        #pragma unroll
        for (int kb = 0; kb < 64; kb += 8) {
            uint32_t a[2][4];
            #pragma unroll
            for (int mi = 0; mi < 2; mi++) {
                int r = am0 + mi * 16;
                a[mi][0] = Ps[r * ASTR + kb + tg];
                a[mi][1] = Ps[(r + 8) * ASTR + kb + tg];
                a[mi][2] = Ps[r * ASTR + kb + tg + 4];
                a[mi][3] = Ps[(r + 8) * ASTR + kb + tg + 4];
            }
            #pragma unroll
            for (int ni = 0; ni < 4; ni++) {
                int n = warp_n * 32 + ni * 8 + g;
                uint32_t b0 = Vt[n * ASTR + kb + tg];
                uint32_t b1 = Vt[n * ASTR + kb + tg + 4];
                mma_tf32(o[0][ni][0], o[0][ni][1], o[0][ni][2], o[0][ni][3],
                         a[0][0], a[0][1], a[0][2], a[0][3], b0, b1);
                mma_tf32(o[1][ni][0], o[1][ni][1], o[1][ni][2], o[1][ni][3],
                         a[1][0], a[1][1], a[1][2], a[1][3], b0, b1);
            }
        }
        __syncthreads();
    }

    // ---- write ctx ----
    #pragma unroll
    for (int mi = 0; mi < 2; mi++) {
        int r = am0 + mi * 16;
        float inv0 = 1.f / l[mi][0], inv1 = 1.f / l[mi][1];
        int t0 = b * 1024 + n0 + r;
        int t1 = t0 + 8;
        #pragma unroll
        for (int ni = 0; ni < 4; ni++) {
            int c = warp_n * 32 + ni * 8 + 2 * tg;
            *(float2*)&ctx[(size_t)t0 * 1024 + h * 64 + c] =
                make_float2(o[mi][ni][0] * inv0, o[mi][ni][1] * inv0);
            *(float2*)&ctx[(size_t)t1 * 1024 + h * 64 + c] =
                make_float2(o[mi][ni][2] * inv1, o[mi][ni][3] * inv1);
        }
    }
}

// ---------------- residual + layernorm over a + sum of nb partials ----------------
__global__ void __launch_bounds__(256)
ln_kernel(const float* __restrict__ a, const float* __restrict__ parts, int nb,
          const float* __restrict__ s, const float* __restrict__ bias,
          float* __restrict__ out) {
    int t = blockIdx.x;
    int base = threadIdx.x << 2;
    size_t off = (size_t)t * DM + base;
    float4 av = *(const float4*)(a + off);
    float v[4] = {av.x, av.y, av.z, av.w};
    for (int p = 0; p < nb; p++) {
        float4 c = *(const float4*)(parts + (size_t)p * TKN * DM + off);
        v[0] += c.x; v[1] += c.y; v[2] += c.z; v[3] += c.w;
    }
    float s1 = v[0] + v[1] + v[2] + v[3];
    float s2 = v[0] * v[0] + v[1] * v[1] + v[2] * v[2] + v[3] * v[3];
    #pragma unroll
    for (int o = 16; o; o >>= 1) {
        s1 += __shfl_xor_sync(0xffffffffu, s1, o);
        s2 += __shfl_xor_sync(0xffffffffu, s2, o);
    }
    __shared__ float w1[8], w2[8];
    __shared__ float sh_mean, sh_inv;
    int warp = threadIdx.x >> 5, lane = threadIdx.x & 31;
    if (lane == 0) { w1[warp] = s1; w2[warp] = s2; }
    __syncthreads();
    if (threadIdx.x == 0) {
        float A = 0.f, B = 0.f;
        #pragma unroll
        for (int i = 0; i < 8; i++) { A += w1[i]; B += w2[i]; }
        float mean = A * (1.f / DM);
        float var = B * (1.f / DM) - mean * mean;
        sh_mean = mean;
        sh_inv = rsqrtf(var + 1e-5f);
    }
    __syncthreads();
    float mean = sh_mean, inv = sh_inv;
    float4 sv = *(const float4*)(s + base);
    float4 biv = *(const float4*)(bias + base);
    float4 ov;
    ov.x = (v[0] - mean) * inv * sv.x + biv.x;
    ov.y = (v[1] - mean) * inv * sv.y + biv.y;
    ov.z = (v[2] - mean) * inv * sv.z + biv.z;
    ov.w = (v[3] - mean) * inv * sv.w + biv.w;
    *(float4*)(out + off) = ov;
}

// ---------------- launch ----------------
extern "C" void kernel_launch(void* const* d_in, const int* in_sizes, int n_in,
                              void* d_out, int out_size) {
    const float* src     = (const float*)d_in[0];
    const unsigned char* mask = (const unsigned char*)d_in[1];
    const float* Wg_attn = (const float*)d_in[2];
    const float* Wqkv    = (const float*)d_in[3];
    const float* bqkv    = (const float*)d_in[4];
    const float* Wo      = (const float*)d_in[5];
    const float* bo      = (const float*)d_in[6];
    const float* Wg_ffn  = (const float*)d_in[7];
    const float* W1      = (const float*)d_in[8];
    const float* b1      = (const float*)d_in[9];
    const float* W2      = (const float*)d_in[10];
    const float* b2      = (const float*)d_in[11];
    const float* ln1_s   = (const float*)d_in[12];
    const float* ln1_b   = (const float*)d_in[13];
    const float* ln2_s   = (const float*)d_in[14];
    const float* ln2_b   = (const float*)d_in[15];
    float* out = (float*)d_out;

    float *qkv, *ctx, *x, *tmp, *hbuf, *gw0, *gw1;
    int *idx0, *idx1, *perm0, *perm1, *te0, *te1;
    cudaGetSymbolAddress((void**)&qkv,  g_qkv);
    cudaGetSymbolAddress((void**)&ctx,  g_ctx);
    cudaGetSymbolAddress((void**)&x,    g_x);
    cudaGetSymbolAddress((void**)&tmp,  g_tmp);
    cudaGetSymbolAddress((void**)&hbuf, g_h);
    cudaGetSymbolAddress((void**)&gw0,  g_gw0);
    cudaGetSymbolAddress((void**)&gw1,  g_gw1);
    cudaGetSymbolAddress((void**)&idx0, g_idx0);
    cudaGetSymbolAddress((void**)&idx1, g_idx1);
    cudaGetSymbolAddress((void**)&perm0, g_perm0);
    cudaGetSymbolAddress((void**)&perm1, g_perm1);
    cudaGetSymbolAddress((void**)&te0,  g_te0);
    cudaGetSymbolAddress((void**)&te1,  g_te1);

    int att_smem = ATT3_SMEM_WORDS * (int)sizeof(uint32_t);
    cudaFuncSetAttribute(attn_mma, cudaFuncAttributeMaxDynamicSharedMemorySize, att_smem);

    // 1. attention gate + grouping
    gate_kernel<<<TKN, 256>>>(src, Wg_attn, idx0, gw0);
    scatter_kernel<<<1, 256>>>(idx0, perm0, te0);
    // 2. QKV projection
    moe_gemm_mma<<<dim3(3 * DM / 128, MAXTILES, 1), 256>>>(
        src, Wqkv, bqkv, gw0, perm0, te0, qkv, DM, 3 * DM, 0, DM);
    // 3. attention (BQ=128)
    attn_mma<<<dim3(1024 / 128, 2 * NH), 256, att_smem>>>(qkv, mask, ctx);
    // 4. output projection, split-K x4
    moe_gemm_mma<<<dim3(DM / 128, MAXTILES, 4), 256>>>(
        ctx, Wo, bo, gw0, perm0, te0, tmp, DM, DM, 0, DM / 4);
    // 5. x = LN1(src + 4 partials)
    ln_kernel<<<TKN, 256>>>(src, tmp, 4, ln1_s, ln1_b, x);
    // 6. ffn gate + grouping
    gate_kernel<<<TKN, 256>>>(x, Wg_ffn, idx1, gw1);
    scatter_kernel<<<1, 256>>>(idx1, perm1, te1);
    // 7. h = gelu(gated W1)
    moe_gemm_mma<<<dim3(FFD / 128, MAXTILES, 1), 256>>>(
        x, W1, b1, gw1, perm1, te1, hbuf, DM, FFD, 1, DM);
    // 8. ffn = gated W2, split-K x8
    moe_gemm_mma<<<dim3(DM / 128, MAXTILES, 8), 256>>>(
        hbuf, W2, b2, gw1, perm1, te1, tmp, FFD, DM, 0, FFD / 8);
    // 9. out = LN2(x + 8 partials)
    ln_kernel<<<TKN, 256>>>(x, tmp, 8, ln2_s, ln2_b, out);
}

// round 10
// speedup vs baseline: 1.7782x; 1.2691x over previous
#include <cuda_runtime.h>
#include <math.h>
#include <stdint.h>

// Problem constants
#define TKN 2048          // B*N tokens
#define DM 1024           // model dim
#define NE 8              // experts
#define FFD 4096          // ffn dim
#define NH 16             // heads
#define HD 64             // head dim
#define PADROWS 3072      // token rows padded to 128 per expert segment
#define MAXTILES 24       // PADROWS/128

// ---------------- scratch (device globals; no allocation allowed) ----------------
__device__ float g_qkv[TKN * 3 * DM];
__device__ float g_ctx[TKN * DM];
__device__ float g_x[TKN * DM];
__device__ float g_tmp[8 * TKN * DM];     // up to 8 split-K partials
__device__ float g_h[TKN * FFD];
__device__ int   g_idx0[TKN];
__device__ int   g_idx1[TKN];
__device__ float g_gw0[TKN];
__device__ float g_gw1[TKN];
__device__ int   g_perm0[PADROWS];
__device__ int   g_perm1[PADROWS];
__device__ int   g_te0[MAXTILES];
__device__ int   g_te1[MAXTILES];

__device__ __forceinline__ uint32_t f2tf32(float x) {
    uint32_t r;
    asm("cvt.rna.tf32.f32 %0, %1;" : "=r"(r) : "f"(x));
    return r;
}
// pack two fp32 -> bf16x2 (lo = first arg's slot: d.lo = b operand, d.hi = a operand)
__device__ __forceinline__ uint32_t pack_bf16(float lo, float hi) {
    uint32_t r;
    asm("cvt.rn.bf16x2.f32 %0, %1, %2;" : "=r"(r) : "f"(hi), "f"(lo));
    return r;
}
__device__ __forceinline__ void mma_tf32(float& c0, float& c1, float& c2, float& c3,
                                         uint32_t a0, uint32_t a1, uint32_t a2, uint32_t a3,
                                         uint32_t b0, uint32_t b1) {
    asm volatile(
        "mma.sync.aligned.m16n8k8.row.col.f32.tf32.tf32.f32 "
        "{%0,%1,%2,%3}, {%4,%5,%6,%7}, {%8,%9}, {%0,%1,%2,%3};"
        : "+f"(c0), "+f"(c1), "+f"(c2), "+f"(c3)
        : "r"(a0), "r"(a1), "r"(a2), "r"(a3), "r"(b0), "r"(b1));
}
__device__ __forceinline__ void mma_bf16(float& c0, float& c1, float& c2, float& c3,
                                         uint32_t a0, uint32_t a1, uint32_t a2, uint32_t a3,
                                         uint32_t b0, uint32_t b1) {
    asm volatile(
        "mma.sync.aligned.m16n8k16.row.col.f32.bf16.bf16.f32 "
        "{%0,%1,%2,%3}, {%4,%5,%6,%7}, {%8,%9}, {%0,%1,%2,%3};"
        : "+f"(c0), "+f"(c1), "+f"(c2), "+f"(c3)
        : "r"(a0), "r"(a1), "r"(a2), "r"(a3), "r"(b0), "r"(b1));
}

// ---------------- gate ----------------
__global__ void gate_kernel(const float* __restrict__ x, const float* __restrict__ Wg,
                            int* __restrict__ idx, float* __restrict__ gw) {
    int t = blockIdx.x;
    int warp = threadIdx.x >> 5, lane = threadIdx.x & 31;
    const float* xr = x + (size_t)t * DM;
    float s = 0.f;
    #pragma unroll 4
    for (int d = lane; d < DM; d += 32) s += xr[d] * Wg[d * NE + warp];
    #pragma unroll
    for (int o = 16; o; o >>= 1) s += __shfl_xor_sync(0xffffffffu, s, o);
    __shared__ float logits[NE];
    if (lane == 0) logits[warp] = s;
    __syncthreads();
    if (threadIdx.x == 0) {
        float best = logits[0]; int bi = 0;
        #pragma unroll
        for (int e = 1; e < NE; e++) if (logits[e] > best) { best = logits[e]; bi = e; }
        float sum = 0.f;
        #pragma unroll
        for (int e = 0; e < NE; e++) sum += expf(logits[e] - best);
        idx[t] = bi;
        gw[t] = 1.f / sum;
    }
}

// ---------------- scatter ----------------
__global__ void scatter_kernel(const int* __restrict__ idx, int* __restrict__ perm,
                               int* __restrict__ tile_expert) {
    __shared__ int cnt[NE];
    __shared__ int cur[NE];
    int tid = threadIdx.x;
    if (tid < NE) cnt[tid] = 0;
    for (int i = tid; i < PADROWS; i += blockDim.x) perm[i] = -1;
    __syncthreads();
    for (int t = tid; t < TKN; t += blockDim.x) atomicAdd(&cnt[idx[t]], 1);
    __syncthreads();
    if (tid == 0) {
        int c = 0;
        for (int e = 0; e < NE; e++) {
            cur[e] = c;
            int tiles = (cnt[e] + 127) >> 7;
            for (int i = 0; i < tiles; i++) tile_expert[(c >> 7) + i] = e;
            c += tiles << 7;
        }
        for (int i = c >> 7; i < MAXTILES; i++) tile_expert[i] = -1;
    }
    __syncthreads();
    for (int t = tid; t < TKN; t += blockDim.x) {
        int p = atomicAdd(&cur[idx[t]], 1);
        perm[p] = t;
    }
}

// ============ bf16 mma.sync (m16n8k16) MoE GEMM with split-K ============
// 128x128 CTA tile, BK=16 (= 8 bf16-pair rows), 8 warps (4M x 2N), warp tile 32x64.
// smem: k-pair-major [8][136] uint32 (each word = bf16x2 of k-even/k-odd).
#define KSTRIDE 136
#define STGW (8 * KSTRIDE)   // words per stage = 1088

__global__ void __launch_bounds__(256, 2)
moe_gemm_mma(const float* __restrict__ In, const float* __restrict__ W,
             const float* __restrict__ bias, const float* __restrict__ gw,
             const int* __restrict__ perm, const int* __restrict__ tile_expert,
             float* __restrict__ Out, int Ktot, int Nout, int gelu_flag, int klen) {
    int e = tile_expert[blockIdx.y];
    if (e < 0) return;
    __shared__ uint32_t SA[2][STGW];
    __shared__ uint32_t SB[2][STGW];

    int tid = threadIdx.x, wid = tid >> 5, lane = tid & 31;
    int g = lane >> 2, tg = lane & 3;
    int warp_m = wid & 3, warp_n = wid >> 2;
    int row0 = blockIdx.y << 7, col0 = blockIdx.x << 7;
    int k0off = blockIdx.z * klen;
    float* OutZ = Out + (size_t)blockIdx.z * TKN * Nout;
    float bsel = (blockIdx.z == 0) ? 1.f : 0.f;

    // A: thread handles row mS (0..127), k-half kqS (0 or 8); stores 4 packed words
    int mS = tid & 127;
    int kqS = (tid >> 7) << 3;
    int kq2 = kqS >> 1;              // pair-row base (0 or 4)
    int tokA = perm[row0 + mS];
    const float* aptr = (tokA >= 0) ? (In + (size_t)tokA * Ktot + k0off + kqS) : In;
    // B: thread handles k rows k2,k2+1 (one pair-row), 4 cols at nB4; one STS.128
    int k2 = (tid >> 5) << 1;
    int kp2 = k2 >> 1;               // pair-row (0..7)
    int nB4 = (tid & 31) << 2;
    const float* bptr = W + ((size_t)e * Ktot + k0off + k2) * Nout + col0 + nB4;

    float acc[2][8][4];
    #pragma unroll
    for (int mi = 0; mi < 2; mi++)
        #pragma unroll
        for (int ni = 0; ni < 8; ni++)
            #pragma unroll
            for (int q = 0; q < 4; q++) acc[mi][ni][q] = 0.f;

    int nchunk = klen >> 4;

    // ---- prologue: chunk 0 into buffer 0 ----
    {
        float4 av0 = make_float4(0.f,0.f,0.f,0.f), av1 = av0;
        if (tokA >= 0) { av0 = *(const float4*)(aptr); av1 = *(const float4*)(aptr + 4); }
        float4 bv0 = *(const float4*)(bptr);
        float4 bv1 = *(const float4*)(bptr + Nout);
        SA[0][(kq2 + 0) * KSTRIDE + mS] = pack_bf16(av0.x, av0.y);
        SA[0][(kq2 + 1) * KSTRIDE + mS] = pack_bf16(av0.z, av0.w);
        SA[0][(kq2 + 2) * KSTRIDE + mS] = pack_bf16(av1.x, av1.y);
        SA[0][(kq2 + 3) * KSTRIDE + mS] = pack_bf16(av1.z, av1.w);
        *(uint4*)&SB[0][kp2 * KSTRIDE + nB4] =
            make_uint4(pack_bf16(bv0.x, bv1.x), pack_bf16(bv0.y, bv1.y),
                       pack_bf16(bv0.z, bv1.z), pack_bf16(bv0.w, bv1.w));
    }
    __syncthreads();

    int am0 = warp_m * 32 + g;
    int bn0 = warp_n * 64 + g;

    for (int c = 0; c < nchunk; c++) {
        int buf = c & 1;
        bool has_next = (c + 1) < nchunk;
        float4 av0, av1, bv0, bv1;
        if (has_next) {
            int k0 = (c + 1) << 4;
            if (tokA >= 0) {
                av0 = *(const float4*)(aptr + k0);
                av1 = *(const float4*)(aptr + k0 + 4);
            } else { av0 = make_float4(0.f,0.f,0.f,0.f); av1 = av0; }
            const float* bp = bptr + (size_t)k0 * Nout;
            bv0 = *(const float4*)(bp);
            bv1 = *(const float4*)(bp + Nout);
        }

        // ---- compute chunk c: one k16 bf16 mma step ----
        const uint32_t* Ab = SA[buf];
        const uint32_t* Bb = SB[buf];
        {
            uint32_t a[2][4];
            #pragma unroll
            for (int mi = 0; mi < 2; mi++) {
                int m = am0 + mi * 16;
                a[mi][0] = Ab[tg * KSTRIDE + m];
                a[mi][1] = Ab[tg * KSTRIDE + m + 8];
                a[mi][2] = Ab[(tg + 4) * KSTRIDE + m];
                a[mi][3] = Ab[(tg + 4) * KSTRIDE + m + 8];
            }
            #pragma unroll
            for (int ni = 0; ni < 8; ni++) {
                int n = bn0 + ni * 8;
                uint32_t b0 = Bb[tg * KSTRIDE + n];
                uint32_t b1 = Bb[(tg + 4) * KSTRIDE + n];
                mma_bf16(acc[0][ni][0], acc[0][ni][1], acc[0][ni][2], acc[0][ni][3],
                         a[0][0], a[0][1], a[0][2], a[0][3], b0, b1);
                mma_bf16(acc[1][ni][0], acc[1][ni][1], acc[1][ni][2], acc[1][ni][3],
                         a[1][0], a[1][1], a[1][2], a[1][3], b0, b1);
            }
        }

        if (has_next) {
            int nb = buf ^ 1;
            SA[nb][(kq2 + 0) * KSTRIDE + mS] = pack_bf16(av0.x, av0.y);
            SA[nb][(kq2 + 1) * KSTRIDE + mS] = pack_bf16(av0.z, av0.w);
            SA[nb][(kq2 + 2) * KSTRIDE + mS] = pack_bf16(av1.x, av1.y);
            SA[nb][(kq2 + 3) * KSTRIDE + mS] = pack_bf16(av1.z, av1.w);
            *(uint4*)&SB[nb][kp2 * KSTRIDE + nB4] =
                make_uint4(pack_bf16(bv0.x, bv1.x), pack_bf16(bv0.y, bv1.y),
                           pack_bf16(bv0.z, bv1.z), pack_bf16(bv0.w, bv1.w));
            __syncthreads();
        }
    }

    // ---- epilogue ----
    int tok[4]; float gwv[4];
    #pragma unroll
    for (int q = 0; q < 4; q++) {
        int r = row0 + warp_m * 32 + g + q * 8;
        tok[q] = perm[r];
        gwv[q] = (tok[q] >= 0) ? gw[tok[q]] : 0.f;
    }
    #pragma unroll
    for (int ni = 0; ni < 8; ni++) {
        int col = col0 + warp_n * 64 + ni * 8 + 2 * tg;
        float2 bs2 = *(const float2*)&bias[(size_t)e * Nout + col];
        bs2.x *= bsel; bs2.y *= bsel;
        #pragma unroll
        for (int mi = 0; mi < 2; mi++) {
            #pragma unroll
            for (int half = 0; half < 2; half++) {
                int q = mi * 2 + half;
                if (tok[q] < 0) continue;
                float v0 = (acc[mi][ni][half * 2 + 0] + bs2.x) * gwv[q];
                float v1 = (acc[mi][ni][half * 2 + 1] + bs2.y) * gwv[q];
                if (gelu_flag) {
                    float c0 = v0 + 0.044715f * v0 * v0 * v0;
                    v0 = 0.5f * v0 * (1.f + tanhf(0.7978845608028654f * c0));
                    float c1 = v1 + 0.044715f * v1 * v1 * v1;
                    v1 = 0.5f * v1 * (1.f + tanhf(0.7978845608028654f * c1));
                }
                *(float2*)&OutZ[(size_t)tok[q] * Nout + col] = make_float2(v0, v1);
            }
        }
    }
}

// ============ flash attention: BQ=128, BK=64, tf32 mma, 8 warps (unchanged R9) ============
#define ASTR 68
#define ATT3_SMEM_WORDS ((128 + 64 + 64 + 128) * ASTR + 256 + 256 + 64)

__global__ void __launch_bounds__(256, 2)
attn_mma(const float* __restrict__ qkv, const unsigned char* __restrict__ mask,
         float* __restrict__ ctx) {
    extern __shared__ uint32_t sm4[];
    uint32_t* Qs = sm4;
    uint32_t* Ks = Qs + 128 * ASTR;
    uint32_t* Vt = Ks + 64 * ASTR;
    uint32_t* Ps = Vt + 64 * ASTR;
    float* redm  = (float*)(Ps + 128 * ASTR);
    float* redl  = redm + 256;
    float* maskS = redl + 256;

    int bh = blockIdx.y;
    int b = bh >> 4, h = bh & 15;
    int n0 = blockIdx.x << 7;
    int tid = threadIdx.x, lane = tid & 31, wid = tid >> 5;
    int g = lane >> 2, tg = lane & 3;
    int warp_m = wid & 3, warp_n = wid >> 2;
    int am0 = warp_m * 32 + g;

    {
        int qrow = tid & 127, qd0 = (tid >> 7) << 5;
        const float* qp = qkv + (size_t)(b * 1024 + n0 + qrow) * 3072 + h * 64 + qd0;
        #pragma unroll
        for (int i = 0; i < 32; i += 4) {
            float4 v = *(const float4*)(qp + i);
            *(uint4*)&Qs[qrow * ASTR + qd0 + i] =
                make_uint4(f2tf32(v.x), f2tf32(v.y), f2tf32(v.z), f2tf32(v.w));
        }
    }

    float o[2][4][4];
    float m[2][2], l[2][2];
    #pragma unroll
    for (int mi = 0; mi < 2; mi++) {
        m[mi][0] = m[mi][1] = -1e30f;
        l[mi][0] = l[mi][1] = 0.f;
        #pragma unroll
        for (int ni = 0; ni < 4; ni++)
            #pragma unroll
            for (int q = 0; q < 4; q++) o[mi][ni][q] = 0.f;
    }

    int lrow = tid & 63, d0 = (tid >> 6) << 4;

    for (int kt = 0; kt < 16; kt++) {
        {
            const float* base = qkv + (size_t)(b * 1024 + kt * 64 + lrow) * 3072 + h * 64 + d0;
            #pragma unroll
            for (int i = 0; i < 16; i += 4) {
                float4 kv = *(const float4*)(base + 1024 + i);
                *(uint4*)&Ks[lrow * ASTR + d0 + i] =
                    make_uint4(f2tf32(kv.x), f2tf32(kv.y), f2tf32(kv.z), f2tf32(kv.w));
            }
            #pragma unroll
            for (int i = 0; i < 16; i += 4) {
                float4 vv = *(const float4*)(base + 2048 + i);
                Vt[(d0 + i + 0) * ASTR + lrow] = f2tf32(vv.x);
                Vt[(d0 + i + 1) * ASTR + lrow] = f2tf32(vv.y);
                Vt[(d0 + i + 2) * ASTR + lrow] = f2tf32(vv.z);
                Vt[(d0 + i + 3) * ASTR + lrow] = f2tf32(vv.w);
            }
            if (tid < 64)
                maskS[tid] = mask[b * 1024 + kt * 64 + tid] ? -10000.f : 0.f;
        }
        __syncthreads();

        float s[2][4][4];
        #pragma unroll
        for (int mi = 0; mi < 2; mi++)
            #pragma unroll
            for (int ni = 0; ni < 4; ni++)
                #pragma unroll
                for (int q = 0; q < 4; q++) s[mi][ni][q] = 0.f;
        #pragma unroll
        for (int kb = 0; kb < 64; kb += 8) {
            uint32_t a[2][4];
            #pragma unroll
            for (int mi = 0; mi < 2; mi++) {
                int r = am0 + mi * 16;
                a[mi][0] = Qs[r * ASTR + kb + tg];
                a[mi][1] = Qs[(r + 8) * ASTR + kb + tg];
                a[mi][2] = Qs[r * ASTR + kb + tg + 4];
                a[mi][3] = Qs[(r + 8) * ASTR + kb + tg + 4];
            }
            #pragma unroll
            for (int ni = 0; ni < 4; ni++) {
                int n = warp_n * 32 + ni * 8 + g;
                uint32_t b0 = Ks[n * ASTR + kb + tg];
                uint32_t b1 = Ks[n * ASTR + kb + tg + 4];
                mma_tf32(s[0][ni][0], s[0][ni][1], s[0][ni][2], s[0][ni][3],
                         a[0][0], a[0][1], a[0][2], a[0][3], b0, b1);
                mma_tf32(s[1][ni][0], s[1][ni][1], s[1][ni][2], s[1][ni][3],
                         a[1][0], a[1][1], a[1][2], a[1][3], b0, b1);
            }
        }
        #pragma unroll
        for (int ni = 0; ni < 4; ni++) {
            int c0 = warp_n * 32 + ni * 8 + 2 * tg;
            float mv0 = maskS[c0], mv1 = maskS[c0 + 1];
            #pragma unroll
            for (int mi = 0; mi < 2; mi++) {
                s[mi][ni][0] = s[mi][ni][0] * 0.125f + mv0;
                s[mi][ni][1] = s[mi][ni][1] * 0.125f + mv1;
                s[mi][ni][2] = s[mi][ni][2] * 0.125f + mv0;
                s[mi][ni][3] = s[mi][ni][3] * 0.125f + mv1;
            }
        }

        float mn[2][2], sc[2][2];
        #pragma unroll
        for (int mi = 0; mi < 2; mi++) {
            float rm0 = -1e30f, rm1 = -1e30f;
            #pragma unroll
            for (int ni = 0; ni < 4; ni++) {
                rm0 = fmaxf(rm0, fmaxf(s[mi][ni][0], s[mi][ni][1]));
                rm1 = fmaxf(rm1, fmaxf(s[mi][ni][2], s[mi][ni][3]));
            }
            rm0 = fmaxf(rm0, __shfl_xor_sync(0xffffffffu, rm0, 1));
            rm0 = fmaxf(rm0, __shfl_xor_sync(0xffffffffu, rm0, 2));
            rm1 = fmaxf(rm1, __shfl_xor_sync(0xffffffffu, rm1, 1));
            rm1 = fmaxf(rm1, __shfl_xor_sync(0xffffffffu, rm1, 2));
            if (tg == 0) {
                int r = am0 + mi * 16;
                redm[warp_n * 128 + r] = rm0;
                redm[warp_n * 128 + r + 8] = rm1;
            }
        }
        __syncthreads();
        #pragma unroll
        for (int mi = 0; mi < 2; mi++) {
            int r = am0 + mi * 16;
            mn[mi][0] = fmaxf(m[mi][0], fmaxf(redm[r], redm[128 + r]));
            mn[mi][1] = fmaxf(m[mi][1], fmaxf(redm[r + 8], redm[128 + r + 8]));
            sc[mi][0] = __expf(m[mi][0] - mn[mi][0]);
            sc[mi][1] = __expf(m[mi][1] - mn[mi][1]);
            m[mi][0] = mn[mi][0]; m[mi][1] = mn[mi][1];
        }

        #pragma unroll
        for (int mi = 0; mi < 2; mi++) {
            int r = am0 + mi * 16;
            float ps0 = 0.f, ps1 = 0.f;
            #pragma unroll
            for (int ni = 0; ni < 4; ni++) {
                int c0 = warp_n * 32 + ni * 8 + 2 * tg;
                s[mi][ni][0] = __expf(s[mi][ni][0] - mn[mi][0]);
                s[mi][ni][1] = __expf(s[mi][ni][1] - mn[mi][0]);
                s[mi][ni][2] = __expf(s[mi][ni][2] - mn[mi][1]);
                s[mi][ni][3] = __expf(s[mi][ni][3] - mn[mi][1]);
                ps0 += s[mi][ni][0] + s[mi][ni][1];
                ps1 += s[mi][ni][2] + s[mi][ni][3];
                Ps[r * ASTR + c0]           = f2tf32(s[mi][ni][0]);
                Ps[r * ASTR + c0 + 1]       = f2tf32(s[mi][ni][1]);
                Ps[(r + 8) * ASTR + c0]     = f2tf32(s[mi][ni][2]);
                Ps[(r + 8) * ASTR + c0 + 1] = f2tf32(s[mi][ni][3]);
            }
            ps0 += __shfl_xor_sync(0xffffffffu, ps0, 1);
            ps0 += __shfl_xor_sync(0xffffffffu, ps0, 2);
            ps1 += __shfl_xor_sync(0xffffffffu, ps1, 1);
            ps1 += __shfl_xor_sync(0xffffffffu, ps1, 2);
            if (tg == 0) {
                redl[warp_n * 128 + r] = ps0;
                redl[warp_n * 128 + r + 8] = ps1;
            }
            #pragma unroll
            for (int ni = 0; ni < 4; ni++) {
                o[mi][ni][0] *= sc[mi][0]; o[mi][ni][1] *= sc[mi][0];
                o[mi][ni][2] *= sc[mi][1]; o[mi][ni][3] *= sc[mi][1];
            }
        }
        __syncthreads();
        #pragma unroll
        for (int mi = 0; mi < 2; mi++) {
            int r = am0 + mi * 16;
            l[mi][0] = l[mi][0] * sc[mi][0] + redl[r] + redl[128 + r];
            l[mi][1] = l[mi][1] * sc[mi][1] + redl[r + 8] + redl[128 + r + 8];
        }

        #pragma unroll
        for (int kb = 0; kb < 64; kb += 8) {
            uint32_t a[2][4];
            #pragma unroll
            for (int mi = 0; mi < 2; mi++) {
                int r = am0 + mi * 16;
                a[mi][0] = Ps[r * ASTR + kb + tg];
                a[mi][1] = Ps[(r + 8) * ASTR + kb + tg];
                a[mi][2] = Ps[r * ASTR + kb + tg + 4];
                a[mi][3] = Ps[(r + 8) * ASTR + kb + tg + 4];
            }
            #pragma unroll
            for (int ni = 0; ni < 4; ni++) {
                int n = warp_n * 32 + ni * 8 + g;
                uint32_t b0 = Vt[n * ASTR + kb + tg];
                uint32_t b1 = Vt[n * ASTR + kb + tg + 4];
                mma_tf32(o[0][ni][0], o[0][ni][1], o[0][ni][2], o[0][ni][3],
                         a[0][0], a[0][1], a[0][2], a[0][3], b0, b1);
                mma_tf32(o[1][ni][0], o[1][ni][1], o[1][ni][2], o[1][ni][3],
                         a[1][0], a[1][1], a[1][2], a[1][3], b0, b1);
            }
        }
        __syncthreads();
    }

    #pragma unroll
    for (int mi = 0; mi < 2; mi++) {
        int r = am0 + mi * 16;
        float inv0 = 1.f / l[mi][0], inv1 = 1.f / l[mi][1];
        int t0 = b * 1024 + n0 + r;
        int t1 = t0 + 8;
        #pragma unroll
        for (int ni = 0; ni < 4; ni++) {
            int c = warp_n * 32 + ni * 8 + 2 * tg;
            *(float2*)&ctx[(size_t)t0 * 1024 + h * 64 + c] =
                make_float2(o[mi][ni][0] * inv0, o[mi][ni][1] * inv0);
            *(float2*)&ctx[(size_t)t1 * 1024 + h * 64 + c] =
                make_float2(o[mi][ni][2] * inv1, o[mi][ni][3] * inv1);
        }
    }
}

// ---------------- residual + layernorm over a + sum of nb partials ----------------
__global__ void __launch_bounds__(256)
ln_kernel(const float* __restrict__ a, const float* __restrict__ parts, int nb,
          const float* __restrict__ s, const float* __restrict__ bias,
          float* __restrict__ out) {
    int t = blockIdx.x;
    int base = threadIdx.x << 2;
    size_t off = (size_t)t * DM + base;
    float4 av = *(const float4*)(a + off);
    float v[4] = {av.x, av.y, av.z, av.w};
    for (int p = 0; p < nb; p++) {
        float4 c = *(const float4*)(parts + (size_t)p * TKN * DM + off);
        v[0] += c.x; v[1] += c.y; v[2] += c.z; v[3] += c.w;
    }
    float s1 = v[0] + v[1] + v[2] + v[3];
    float s2 = v[0] * v[0] + v[1] * v[1] + v[2] * v[2] + v[3] * v[3];
    #pragma unroll
    for (int o = 16; o; o >>= 1) {
        s1 += __shfl_xor_sync(0xffffffffu, s1, o);
        s2 += __shfl_xor_sync(0xffffffffu, s2, o);
    }
    __shared__ float w1[8], w2[8];
    __shared__ float sh_mean, sh_inv;
    int warp = threadIdx.x >> 5, lane = threadIdx.x & 31;
    if (lane == 0) { w1[warp] = s1; w2[warp] = s2; }
    __syncthreads();
    if (threadIdx.x == 0) {
        float A = 0.f, B = 0.f;
        #pragma unroll
        for (int i = 0; i < 8; i++) { A += w1[i]; B += w2[i]; }
        float mean = A * (1.f / DM);
        float var = B * (1.f / DM) - mean * mean;
        sh_mean = mean;
        sh_inv = rsqrtf(var + 1e-5f);
    }
    __syncthreads();
    float mean = sh_mean, inv = sh_inv;
    float4 sv = *(const float4*)(s + base);
    float4 biv = *(const float4*)(bias + base);
    float4 ov;
    ov.x = (v[0] - mean) * inv * sv.x + biv.x;
    ov.y = (v[1] - mean) * inv * sv.y + biv.y;
    ov.z = (v[2] - mean) * inv * sv.z + biv.z;
    ov.w = (v[3] - mean) * inv * sv.w + biv.w;
    *(float4*)(out + off) = ov;
}

// ---------------- launch ----------------
extern "C" void kernel_launch(void* const* d_in, const int* in_sizes, int n_in,
                              void* d_out, int out_size) {
    const float* src     = (const float*)d_in[0];
    const unsigned char* mask = (const unsigned char*)d_in[1];
    const float* Wg_attn = (const float*)d_in[2];
    const float* Wqkv    = (const float*)d_in[3];
    const float* bqkv    = (const float*)d_in[4];
    const float* Wo      = (const float*)d_in[5];
    const float* bo      = (const float*)d_in[6];
    const float* Wg_ffn  = (const float*)d_in[7];
    const float* W1      = (const float*)d_in[8];
    const float* b1      = (const float*)d_in[9];
    const float* W2      = (const float*)d_in[10];
    const float* b2      = (const float*)d_in[11];
    const float* ln1_s   = (const float*)d_in[12];
    const float* ln1_b   = (const float*)d_in[13];
    const float* ln2_s   = (const float*)d_in[14];
    const float* ln2_b   = (const float*)d_in[15];
    float* out = (float*)d_out;

    float *qkv, *ctx, *x, *tmp, *hbuf, *gw0, *gw1;
    int *idx0, *idx1, *perm0, *perm1, *te0, *te1;
    cudaGetSymbolAddress((void**)&qkv,  g_qkv);
    cudaGetSymbolAddress((void**)&ctx,  g_ctx);
    cudaGetSymbolAddress((void**)&x,    g_x);
    cudaGetSymbolAddress((void**)&tmp,  g_tmp);
    cudaGetSymbolAddress((void**)&hbuf, g_h);
    cudaGetSymbolAddress((void**)&gw0,  g_gw0);
    cudaGetSymbolAddress((void**)&gw1,  g_gw1);
    cudaGetSymbolAddress((void**)&idx0, g_idx0);
    cudaGetSymbolAddress((void**)&idx1, g_idx1);
    cudaGetSymbolAddress((void**)&perm0, g_perm0);
    cudaGetSymbolAddress((void**)&perm1, g_perm1);
    cudaGetSymbolAddress((void**)&te0,  g_te0);
    cudaGetSymbolAddress((void**)&te1,  g_te1);

    int att_smem = ATT3_SMEM_WORDS * (int)sizeof(uint32_t);
    cudaFuncSetAttribute(attn_mma, cudaFuncAttributeMaxDynamicSharedMemorySize, att_smem);

    // 1. attention gate + grouping
    gate_kernel<<<TKN, 256>>>(src, Wg_attn, idx0, gw0);
    scatter_kernel<<<1, 256>>>(idx0, perm0, te0);
    // 2. QKV projection (bf16 mma)
    moe_gemm_mma<<<dim3(3 * DM / 128, MAXTILES, 1), 256>>>(
        src, Wqkv, bqkv, gw0, perm0, te0, qkv, DM, 3 * DM, 0, DM);
    // 3. attention (BQ=128, tf32)
    attn_mma<<<dim3(1024 / 128, 2 * NH), 256, att_smem>>>(qkv, mask, ctx);
    // 4. output projection, split-K x4
    moe_gemm_mma<<<dim3(DM / 128, MAXTILES, 4), 256>>>(
        ctx, Wo, bo, gw0, perm0, te0, tmp, DM, DM, 0, DM / 4);
    // 5. x = LN1(src + 4 partials)
    ln_kernel<<<TKN, 256>>>(src, tmp, 4, ln1_s, ln1_b, x);
    // 6. ffn gate + grouping
    gate_kernel<<<TKN, 256>>>(x, Wg_ffn, idx1, gw1);
    scatter_kernel<<<1, 256>>>(idx1, perm1, te1);
    // 7. h = gelu(gated W1)
    moe_gemm_mma<<<dim3(FFD / 128, MAXTILES, 1), 256>>>(
        x, W1, b1, gw1, perm1, te1, hbuf, DM, FFD, 1, DM);
    // 8. ffn = gated W2, split-K x8
    moe_gemm_mma<<<dim3(DM / 128, MAXTILES, 8), 256>>>(
        hbuf, W2, b2, gw1, perm1, te1, tmp, FFD, DM, 0, FFD / 8);
    // 9. out = LN2(x + 8 partials)
    ln_kernel<<<TKN, 256>>>(x, tmp, 8, ln2_s, ln2_b, out);
}

// round 11
// speedup vs baseline: 1.9278x; 1.0841x over previous
#include <cuda_runtime.h>
#include <math.h>
#include <stdint.h>

// Problem constants
#define TKN 2048          // B*N tokens
#define DM 1024           // model dim
#define NE 8              // experts
#define FFD 4096          // ffn dim
#define NH 16             // heads
#define HD 64             // head dim
#define PADROWS 3072      // token rows padded to 128 per expert segment
#define MAXTILES 24       // PADROWS/128

// ---------------- scratch (device globals; no allocation allowed) ----------------
__device__ float g_qkv[TKN * 3 * DM];
__device__ float g_ctx[TKN * DM];
__device__ float g_x[TKN * DM];
__device__ float g_tmp[8 * TKN * DM];     // up to 8 split-K partials
__device__ float g_h[TKN * FFD];
__device__ int   g_idx0[TKN];
__device__ int   g_idx1[TKN];
__device__ float g_gw0[TKN];
__device__ float g_gw1[TKN];
__device__ int   g_perm0[PADROWS];
__device__ int   g_perm1[PADROWS];
__device__ int   g_te0[MAXTILES];
__device__ int   g_te1[MAXTILES];

// pack two fp32 -> bf16x2 (first arg -> low half = even-k slot)
__device__ __forceinline__ uint32_t pack_bf16(float lo, float hi) {
    uint32_t r;
    asm("cvt.rn.bf16x2.f32 %0, %1, %2;" : "=r"(r) : "f"(hi), "f"(lo));
    return r;
}
__device__ __forceinline__ void mma_bf16(float& c0, float& c1, float& c2, float& c3,
                                         uint32_t a0, uint32_t a1, uint32_t a2, uint32_t a3,
                                         uint32_t b0, uint32_t b1) {
    asm volatile(
        "mma.sync.aligned.m16n8k16.row.col.f32.bf16.bf16.f32 "
        "{%0,%1,%2,%3}, {%4,%5,%6,%7}, {%8,%9}, {%0,%1,%2,%3};"
        : "+f"(c0), "+f"(c1), "+f"(c2), "+f"(c3)
        : "r"(a0), "r"(a1), "r"(a2), "r"(a3), "r"(b0), "r"(b1));
}

// ---------------- gate ----------------
__global__ void gate_kernel(const float* __restrict__ x, const float* __restrict__ Wg,
                            int* __restrict__ idx, float* __restrict__ gw) {
    int t = blockIdx.x;
    int warp = threadIdx.x >> 5, lane = threadIdx.x & 31;
    const float* xr = x + (size_t)t * DM;
    float s = 0.f;
    #pragma unroll 4
    for (int d = lane; d < DM; d += 32) s += xr[d] * Wg[d * NE + warp];
    #pragma unroll
    for (int o = 16; o; o >>= 1) s += __shfl_xor_sync(0xffffffffu, s, o);
    __shared__ float logits[NE];
    if (lane == 0) logits[warp] = s;
    __syncthreads();
    if (threadIdx.x == 0) {
        float best = logits[0]; int bi = 0;
        #pragma unroll
        for (int e = 1; e < NE; e++) if (logits[e] > best) { best = logits[e]; bi = e; }
        float sum = 0.f;
        #pragma unroll
        for (int e = 0; e < NE; e++) sum += expf(logits[e] - best);
        idx[t] = bi;
        gw[t] = 1.f / sum;
    }
}

// ---------------- scatter ----------------
__global__ void scatter_kernel(const int* __restrict__ idx, int* __restrict__ perm,
                               int* __restrict__ tile_expert) {
    __shared__ int cnt[NE];
    __shared__ int cur[NE];
    int tid = threadIdx.x;
    if (tid < NE) cnt[tid] = 0;
    for (int i = tid; i < PADROWS; i += blockDim.x) perm[i] = -1;
    __syncthreads();
    for (int t = tid; t < TKN; t += blockDim.x) atomicAdd(&cnt[idx[t]], 1);
    __syncthreads();
    if (tid == 0) {
        int c = 0;
        for (int e = 0; e < NE; e++) {
            cur[e] = c;
            int tiles = (cnt[e] + 127) >> 7;
            for (int i = 0; i < tiles; i++) tile_expert[(c >> 7) + i] = e;
            c += tiles << 7;
        }
        for (int i = c >> 7; i < MAXTILES; i++) tile_expert[i] = -1;
    }
    __syncthreads();
    for (int t = tid; t < TKN; t += blockDim.x) {
        int p = atomicAdd(&cur[idx[t]], 1);
        perm[p] = t;
    }
}

// ============ bf16 mma.sync MoE GEMM, BK=32, split-K ============
// 128x128 CTA tile, BK=32 (16 bf16-pair rows/stage), 8 warps (4M x 2N), warp tile 32x64.
// smem: pair-major [16][136] uint32 words (word = bf16x2 of k-even/k-odd).
#define KSTRIDE 136
#define STGW (16 * KSTRIDE)   // 2176 words per tile per stage

__global__ void __launch_bounds__(256, 2)
moe_gemm_mma(const float* __restrict__ In, const float* __restrict__ W,
             const float* __restrict__ bias, const float* __restrict__ gw,
             const int* __restrict__ perm, const int* __restrict__ tile_expert,
             float* __restrict__ Out, int Ktot, int Nout, int gelu_flag, int klen) {
    int e = tile_expert[blockIdx.y];
    if (e < 0) return;
    __shared__ uint32_t SA[2][STGW];
    __shared__ uint32_t SB[2][STGW];

    int tid = threadIdx.x, wid = tid >> 5, lane = tid & 31;
    int g = lane >> 2, tg = lane & 3;
    int warp_m = wid & 3, warp_n = wid >> 2;
    int row0 = blockIdx.y << 7, col0 = blockIdx.x << 7;
    int k0off = blockIdx.z * klen;
    float* OutZ = Out + (size_t)blockIdx.z * TKN * Nout;
    float bsel = (blockIdx.z == 0) ? 1.f : 0.f;

    // A: one thread per row (mS), k-half = half*16 (16 floats -> 8 pair-words)
    int mS = tid & 127;
    int half = tid >> 7;
    int kq2 = half << 3;                 // pair base: 0 or 8
    int tokA = perm[row0 + mS];
    const float* aptr = (tokA >= 0) ? (In + (size_t)tokA * Ktot + k0off + (half << 4)) : In;
    // B: 4 k-rows per thread (k4..k4+3 = pairs kp,kp+1), 4 cols at nB4
    int k4 = (tid >> 5) << 2;
    int kp = k4 >> 1;
    int nB4 = (tid & 31) << 2;
    const float* bptr = W + ((size_t)e * Ktot + k0off + k4) * Nout + col0 + nB4;

    float acc[2][8][4];
    #pragma unroll
    for (int mi = 0; mi < 2; mi++)
        #pragma unroll
        for (int ni = 0; ni < 8; ni++)
            #pragma unroll
            for (int q = 0; q < 4; q++) acc[mi][ni][q] = 0.f;

    int nchunk = klen >> 5;

    // ---- prologue: chunk 0 into buffer 0 ----
    {
        float4 av[4], bv[4];
        #pragma unroll
        for (int i = 0; i < 4; i++)
            av[i] = (tokA >= 0) ? *(const float4*)(aptr + 4 * i)
                                : make_float4(0.f, 0.f, 0.f, 0.f);
        #pragma unroll
        for (int i = 0; i < 4; i++)
            bv[i] = *(const float4*)(bptr + (size_t)i * Nout);
        #pragma unroll
        for (int i = 0; i < 4; i++) {
            SA[0][(kq2 + 2 * i) * KSTRIDE + mS]     = pack_bf16(av[i].x, av[i].y);
            SA[0][(kq2 + 2 * i + 1) * KSTRIDE + mS] = pack_bf16(av[i].z, av[i].w);
        }
        *(uint4*)&SB[0][kp * KSTRIDE + nB4] =
            make_uint4(pack_bf16(bv[0].x, bv[1].x), pack_bf16(bv[0].y, bv[1].y),
                       pack_bf16(bv[0].z, bv[1].z), pack_bf16(bv[0].w, bv[1].w));
        *(uint4*)&SB[0][(kp + 1) * KSTRIDE + nB4] =
            make_uint4(pack_bf16(bv[2].x, bv[3].x), pack_bf16(bv[2].y, bv[3].y),
                       pack_bf16(bv[2].z, bv[3].z), pack_bf16(bv[2].w, bv[3].w));
    }
    __syncthreads();

    int am0 = warp_m * 32 + g;
    int bn0 = warp_n * 64 + g;

    for (int c = 0; c < nchunk; c++) {
        int buf = c & 1;
        bool has_next = (c + 1) < nchunk;
        float4 av[4], bv[4];
        if (has_next) {
            int k0 = (c + 1) << 5;
            #pragma unroll
            for (int i = 0; i < 4; i++)
                av[i] = (tokA >= 0) ? *(const float4*)(aptr + k0 + 4 * i)
                                    : make_float4(0.f, 0.f, 0.f, 0.f);
            const float* bp = bptr + (size_t)k0 * Nout;
            #pragma unroll
            for (int i = 0; i < 4; i++)
                bv[i] = *(const float4*)(bp + (size_t)i * Nout);
        }

        // ---- compute chunk c: two k16 bf16 mma steps ----
        const uint32_t* Ab = SA[buf];
        const uint32_t* Bb = SB[buf];
        #pragma unroll
        for (int ks = 0; ks < 2; ks++) {
            int kb = ks << 3;
            uint32_t a[2][4];
            #pragma unroll
            for (int mi = 0; mi < 2; mi++) {
                int m = am0 + mi * 16;
                a[mi][0] = Ab[(kb + tg) * KSTRIDE + m];
                a[mi][1] = Ab[(kb + tg) * KSTRIDE + m + 8];
                a[mi][2] = Ab[(kb + tg + 4) * KSTRIDE + m];
                a[mi][3] = Ab[(kb + tg + 4) * KSTRIDE + m + 8];
            }
            #pragma unroll
            for (int ni = 0; ni < 8; ni++) {
                int n = bn0 + ni * 8;
                uint32_t b0 = Bb[(kb + tg) * KSTRIDE + n];
                uint32_t b1 = Bb[(kb + tg + 4) * KSTRIDE + n];
                mma_bf16(acc[0][ni][0], acc[0][ni][1], acc[0][ni][2], acc[0][ni][3],
                         a[0][0], a[0][1], a[0][2], a[0][3], b0, b1);
                mma_bf16(acc[1][ni][0], acc[1][ni][1], acc[1][ni][2], acc[1][ni][3],
                         a[1][0], a[1][1], a[1][2], a[1][3], b0, b1);
            }
        }

        if (has_next) {
            int nb = buf ^ 1;
            #pragma unroll
            for (int i = 0; i < 4; i++) {
                SA[nb][(kq2 + 2 * i) * KSTRIDE + mS]     = pack_bf16(av[i].x, av[i].y);
                SA[nb][(kq2 + 2 * i + 1) * KSTRIDE + mS] = pack_bf16(av[i].z, av[i].w);
            }
            *(uint4*)&SB[nb][kp * KSTRIDE + nB4] =
                make_uint4(pack_bf16(bv[0].x, bv[1].x), pack_bf16(bv[0].y, bv[1].y),
                           pack_bf16(bv[0].z, bv[1].z), pack_bf16(bv[0].w, bv[1].w));
            *(uint4*)&SB[nb][(kp + 1) * KSTRIDE + nB4] =
                make_uint4(pack_bf16(bv[2].x, bv[3].x), pack_bf16(bv[2].y, bv[3].y),
                           pack_bf16(bv[2].z, bv[3].z), pack_bf16(bv[2].w, bv[3].w));
            __syncthreads();
        }
    }

    // ---- epilogue ----
    int tok[4]; float gwv[4];
    #pragma unroll
    for (int q = 0; q < 4; q++) {
        int r = row0 + warp_m * 32 + g + q * 8;
        tok[q] = perm[r];
        gwv[q] = (tok[q] >= 0) ? gw[tok[q]] : 0.f;
    }
    #pragma unroll
    for (int ni = 0; ni < 8; ni++) {
        int col = col0 + warp_n * 64 + ni * 8 + 2 * tg;
        float2 bs2 = *(const float2*)&bias[(size_t)e * Nout + col];
        bs2.x *= bsel; bs2.y *= bsel;
        #pragma unroll
        for (int mi = 0; mi < 2; mi++) {
            #pragma unroll
            for (int half2 = 0; half2 < 2; half2++) {
                int q = mi * 2 + half2;
                if (tok[q] < 0) continue;
                float v0 = (acc[mi][ni][half2 * 2 + 0] + bs2.x) * gwv[q];
                float v1 = (acc[mi][ni][half2 * 2 + 1] + bs2.y) * gwv[q];
                if (gelu_flag) {
                    float c0 = v0 + 0.044715f * v0 * v0 * v0;
                    v0 = 0.5f * v0 * (1.f + tanhf(0.7978845608028654f * c0));
                    float c1 = v1 + 0.044715f * v1 * v1 * v1;
                    v1 = 0.5f * v1 * (1.f + tanhf(0.7978845608028654f * c1));
                }
                *(float2*)&OutZ[(size_t)tok[q] * Nout + col] = make_float2(v0, v1);
            }
        }
    }
}

// ============ flash attention: BQ=128, BK=64, bf16 mma, 8 warps (4M x 2N) ============
// Packed bf16-pair layouts, stride 36 (== 4 mod 32 -> conflict-free fragment LDS).
// Qs[128][36] (pairs over d), Ks[64][36] (key rows, pairs over d),
// Vt[64][36] (d rows, pairs over keys), Ps[128][36] (pairs over keys).
#define QSTR 36
#define ATT4_SMEM_WORDS ((128 + 64 + 64 + 128) * QSTR + 256 + 256 + 64)

__global__ void __launch_bounds__(256, 2)
attn_mma(const float* __restrict__ qkv, const unsigned char* __restrict__ mask,
         float* __restrict__ ctx) {
    extern __shared__ uint32_t sm4[];
    uint32_t* Qs = sm4;                     // [128][36]
    uint32_t* Ks = Qs + 128 * QSTR;         // [64][36]
    uint32_t* Vt = Ks + 64 * QSTR;          // [64][36]
    uint32_t* Ps = Vt + 64 * QSTR;          // [128][36]
    float* redm  = (float*)(Ps + 128 * QSTR);  // [2][128]
    float* redl  = redm + 256;                 // [2][128]
    float* maskS = redl + 256;                 // [64]

    int bh = blockIdx.y;
    int b = bh >> 4, h = bh & 15;
    int n0 = blockIdx.x << 7;
    int tid = threadIdx.x, lane = tid & 31, wid = tid >> 5;
    int g = lane >> 2, tg = lane & 3;
    int warp_m = wid & 3, warp_n = wid >> 2;
    int am0 = warp_m * 32 + g;

    // ---- load Q tile (128x64 -> bf16 pairs) ----
    {
        int qrow = tid & 127, qd0 = (tid >> 7) << 5;  // 32 d-values per thread
        int qp0 = qd0 >> 1;
        const float* qp = qkv + (size_t)(b * 1024 + n0 + qrow) * 3072 + h * 64 + qd0;
        #pragma unroll
        for (int i = 0; i < 8; i++) {
            float4 v = *(const float4*)(qp + 4 * i);
            Qs[qrow * QSTR + qp0 + 2 * i]     = pack_bf16(v.x, v.y);
            Qs[qrow * QSTR + qp0 + 2 * i + 1] = pack_bf16(v.z, v.w);
        }
    }

    float o[2][4][4];
    float m[2][2], l[2][2];
    #pragma unroll
    for (int mi = 0; mi < 2; mi++) {
        m[mi][0] = m[mi][1] = -1e30f;
        l[mi][0] = l[mi][1] = 0.f;
        #pragma unroll
        for (int ni = 0; ni < 4; ni++)
            #pragma unroll
            for (int q = 0; q < 4; q++) o[mi][ni][q] = 0.f;
    }

    int krow = tid & 63, kd0 = (tid >> 6) << 4;   // K loader: 64 keys x 16 d
    int vkp = tid & 31, vd0 = (tid >> 5) << 3;    // V loader: 32 key-pairs x 8 d

    for (int kt = 0; kt < 16; kt++) {
        // ---- load K (bf16 pairs over d) + V (transposed, bf16 pairs over keys) ----
        {
            const float* kbase = qkv + (size_t)(b * 1024 + kt * 64 + krow) * 3072 + h * 64 + 1024 + kd0;
            int kp0 = kd0 >> 1;
            #pragma unroll
            for (int i = 0; i < 4; i++) {
                float4 kv = *(const float4*)(kbase + 4 * i);
                Ks[krow * QSTR + kp0 + 2 * i]     = pack_bf16(kv.x, kv.y);
                Ks[krow * QSTR + kp0 + 2 * i + 1] = pack_bf16(kv.z, kv.w);
            }
            const float* v0p = qkv + (size_t)(b * 1024 + kt * 64 + 2 * vkp) * 3072 + h * 64 + 2048 + vd0;
            const float* v1p = v0p + 3072;
            float4 va0 = *(const float4*)(v0p);
            float4 va1 = *(const float4*)(v0p + 4);
            float4 vb0 = *(const float4*)(v1p);
            float4 vb1 = *(const float4*)(v1p + 4);
            Vt[(vd0 + 0) * QSTR + vkp] = pack_bf16(va0.x, vb0.x);
            Vt[(vd0 + 1) * QSTR + vkp] = pack_bf16(va0.y, vb0.y);
            Vt[(vd0 + 2) * QSTR + vkp] = pack_bf16(va0.z, vb0.z);
            Vt[(vd0 + 3) * QSTR + vkp] = pack_bf16(va0.w, vb0.w);
            Vt[(vd0 + 4) * QSTR + vkp] = pack_bf16(va1.x, vb1.x);
            Vt[(vd0 + 5) * QSTR + vkp] = pack_bf16(va1.y, vb1.y);
            Vt[(vd0 + 6) * QSTR + vkp] = pack_bf16(va1.z, vb1.z);
            Vt[(vd0 + 7) * QSTR + vkp] = pack_bf16(va1.w, vb1.w);
            if (tid < 64)
                maskS[tid] = mask[b * 1024 + kt * 64 + tid] ? -10000.f : 0.f;
        }
        __syncthreads();

        // ---- S = Q K^T (bf16, 4 k16 steps over 32 d-pairs) ----
        float s[2][4][4];
        #pragma unroll
        for (int mi = 0; mi < 2; mi++)
            #pragma unroll
            for (int ni = 0; ni < 4; ni++)
                #pragma unroll
                for (int q = 0; q < 4; q++) s[mi][ni][q] = 0.f;
        #pragma unroll
        for (int kb = 0; kb < 32; kb += 8) {
            uint32_t a[2][4];
            #pragma unroll
            for (int mi = 0; mi < 2; mi++) {
                int r = am0 + mi * 16;
                a[mi][0] = Qs[r * QSTR + kb + tg];
                a[mi][1] = Qs[(r + 8) * QSTR + kb + tg];
                a[mi][2] = Qs[r * QSTR + kb + tg + 4];
                a[mi][3] = Qs[(r + 8) * QSTR + kb + tg + 4];
            }
            #pragma unroll
            for (int ni = 0; ni < 4; ni++) {
                int n = warp_n * 32 + ni * 8 + g;
                uint32_t b0 = Ks[n * QSTR + kb + tg];
                uint32_t b1 = Ks[n * QSTR + kb + tg + 4];
                mma_bf16(s[0][ni][0], s[0][ni][1], s[0][ni][2], s[0][ni][3],
                         a[0][0], a[0][1], a[0][2], a[0][3], b0, b1);
                mma_bf16(s[1][ni][0], s[1][ni][1], s[1][ni][2], s[1][ni][3],
                         a[1][0], a[1][1], a[1][2], a[1][3], b0, b1);
            }
        }
        // ---- scale + mask ----
        #pragma unroll
        for (int ni = 0; ni < 4; ni++) {
            int c0 = warp_n * 32 + ni * 8 + 2 * tg;
            float mv0 = maskS[c0], mv1 = maskS[c0 + 1];
            #pragma unroll
            for (int mi = 0; mi < 2; mi++) {
                s[mi][ni][0] = s[mi][ni][0] * 0.125f + mv0;
                s[mi][ni][1] = s[mi][ni][1] * 0.125f + mv1;
                s[mi][ni][2] = s[mi][ni][2] * 0.125f + mv0;
                s[mi][ni][3] = s[mi][ni][3] * 0.125f + mv1;
            }
        }

        // ---- row max ----
        float mn[2][2], sc[2][2];
        #pragma unroll
        for (int mi = 0; mi < 2; mi++) {
            float rm0 = -1e30f, rm1 = -1e30f;
            #pragma unroll
            for (int ni = 0; ni < 4; ni++) {
                rm0 = fmaxf(rm0, fmaxf(s[mi][ni][0], s[mi][ni][1]));
                rm1 = fmaxf(rm1, fmaxf(s[mi][ni][2], s[mi][ni][3]));
            }
            rm0 = fmaxf(rm0, __shfl_xor_sync(0xffffffffu, rm0, 1));
            rm0 = fmaxf(rm0, __shfl_xor_sync(0xffffffffu, rm0, 2));
            rm1 = fmaxf(rm1, __shfl_xor_sync(0xffffffffu, rm1, 1));
            rm1 = fmaxf(rm1, __shfl_xor_sync(0xffffffffu, rm1, 2));
            if (tg == 0) {
                int r = am0 + mi * 16;
                redm[warp_n * 128 + r] = rm0;
                redm[warp_n * 128 + r + 8] = rm1;
            }
        }
        __syncthreads();
        #pragma unroll
        for (int mi = 0; mi < 2; mi++) {
            int r = am0 + mi * 16;
            mn[mi][0] = fmaxf(m[mi][0], fmaxf(redm[r], redm[128 + r]));
            mn[mi][1] = fmaxf(m[mi][1], fmaxf(redm[r + 8], redm[128 + r + 8]));
            sc[mi][0] = __expf(m[mi][0] - mn[mi][0]);
            sc[mi][1] = __expf(m[mi][1] - mn[mi][1]);
            m[mi][0] = mn[mi][0]; m[mi][1] = mn[mi][1];
        }

        // ---- p = exp(s-m), write Ps (bf16 pairs), partial sums ----
        #pragma unroll
        for (int mi = 0; mi < 2; mi++) {
            int r = am0 + mi * 16;
            float ps0 = 0.f, ps1 = 0.f;
            #pragma unroll
            for (int ni = 0; ni < 4; ni++) {
                int cw = warp_n * 16 + ni * 4 + tg;   // key-pair word index
                s[mi][ni][0] = __expf(s[mi][ni][0] - mn[mi][0]);
                s[mi][ni][1] = __expf(s[mi][ni][1] - mn[mi][0]);
                s[mi][ni][2] = __expf(s[mi][ni][2] - mn[mi][1]);
                s[mi][ni][3] = __expf(s[mi][ni][3] - mn[mi][1]);
                ps0 += s[mi][ni][0] + s[mi][ni][1];
                ps1 += s[mi][ni][2] + s[mi][ni][3];
                Ps[r * QSTR + cw]       = pack_bf16(s[mi][ni][0], s[mi][ni][1]);
                Ps[(r + 8) * QSTR + cw] = pack_bf16(s[mi][ni][2], s[mi][ni][3]);
            }
            ps0 += __shfl_xor_sync(0xffffffffu, ps0, 1);
            ps0 += __shfl_xor_sync(0xffffffffu, ps0, 2);
            ps1 += __shfl_xor_sync(0xffffffffu, ps1, 1);
            ps1 += __shfl_xor_sync(0xffffffffu, ps1, 2);
            if (tg == 0) {
                redl[warp_n * 128 + r] = ps0;
                redl[warp_n * 128 + r + 8] = ps1;
            }
            #pragma unroll
            for (int ni = 0; ni < 4; ni++) {
                o[mi][ni][0] *= sc[mi][0]; o[mi][ni][1] *= sc[mi][0];
                o[mi][ni][2] *= sc[mi][1]; o[mi][ni][3] *= sc[mi][1];
            }
        }
        __syncthreads();
        #pragma unroll
        for (int mi = 0; mi < 2; mi++) {
            int r = am0 + mi * 16;
            l[mi][0] = l[mi][0] * sc[mi][0] + redl[r] + redl[128 + r];
            l[mi][1] = l[mi][1] * sc[mi][1] + redl[r + 8] + redl[128 + r + 8];
        }

        // ---- O += P V (bf16, 4 k16 steps over 32 key-pairs) ----
        #pragma unroll
        for (int kb = 0; kb < 32; kb += 8) {
            uint32_t a[2][4];
            #pragma unroll
            for (int mi = 0; mi < 2; mi++) {
                int r = am0 + mi * 16;
                a[mi][0] = Ps[r * QSTR + kb + tg];
                a[mi][1] = Ps[(r + 8) * QSTR + kb + tg];
                a[mi][2] = Ps[r * QSTR + kb + tg + 4];
                a[mi][3] = Ps[(r + 8) * QSTR + kb + tg + 4];
            }
            #pragma unroll
            for (int ni = 0; ni < 4; ni++) {
                int n = warp_n * 32 + ni * 8 + g;   // output d index
                uint32_t b0 = Vt[n * QSTR + kb + tg];
                uint32_t b1 = Vt[n * QSTR + kb + tg + 4];
                mma_bf16(o[0][ni][0], o[0][ni][1], o[0][ni][2], o[0][ni][3],
                         a[0][0], a[0][1], a[0][2], a[0][3], b0, b1);
                mma_bf16(o[1][ni][0], o[1][ni][1], o[1][ni][2], o[1][ni][3],
                         a[1][0], a[1][1], a[1][2], a[1][3], b0, b1);
            }
        }
        __syncthreads();
    }

    // ---- write ctx ----
    #pragma unroll
    for (int mi = 0; mi < 2; mi++) {
        int r = am0 + mi * 16;
        float inv0 = 1.f / l[mi][0], inv1 = 1.f / l[mi][1];
        int t0 = b * 1024 + n0 + r;
        int t1 = t0 + 8;
        #pragma unroll
        for (int ni = 0; ni < 4; ni++) {
            int c = warp_n * 32 + ni * 8 + 2 * tg;
            *(float2*)&ctx[(size_t)t0 * 1024 + h * 64 + c] =
                make_float2(o[mi][ni][0] * inv0, o[mi][ni][1] * inv0);
            *(float2*)&ctx[(size_t)t1 * 1024 + h * 64 + c] =
                make_float2(o[mi][ni][2] * inv1, o[mi][ni][3] * inv1);
        }
    }
}

// ---------------- residual + layernorm over a + sum of nb partials ----------------
__global__ void __launch_bounds__(256)
ln_kernel(const float* __restrict__ a, const float* __restrict__ parts, int nb,
          const float* __restrict__ s, const float* __restrict__ bias,
          float* __restrict__ out) {
    int t = blockIdx.x;
    int base = threadIdx.x << 2;
    size_t off = (size_t)t * DM + base;
    float4 av = *(const float4*)(a + off);
    float v[4] = {av.x, av.y, av.z, av.w};
    for (int p = 0; p < nb; p++) {
        float4 c = *(const float4*)(parts + (size_t)p * TKN * DM + off);
        v[0] += c.x; v[1] += c.y; v[2] += c.z; v[3] += c.w;
    }
    float s1 = v[0] + v[1] + v[2] + v[3];
    float s2 = v[0] * v[0] + v[1] * v[1] + v[2] * v[2] + v[3] * v[3];
    #pragma unroll
    for (int o = 16; o; o >>= 1) {
        s1 += __shfl_xor_sync(0xffffffffu, s1, o);
        s2 += __shfl_xor_sync(0xffffffffu, s2, o);
    }
    __shared__ float w1[8], w2[8];
    __shared__ float sh_mean, sh_inv;
    int warp = threadIdx.x >> 5, lane = threadIdx.x & 31;
    if (lane == 0) { w1[warp] = s1; w2[warp] = s2; }
    __syncthreads();
    if (threadIdx.x == 0) {
        float A = 0.f, B = 0.f;
        #pragma unroll
        for (int i = 0; i < 8; i++) { A += w1[i]; B += w2[i]; }
        float mean = A * (1.f / DM);
        float var = B * (1.f / DM) - mean * mean;
        sh_mean = mean;
        sh_inv = rsqrtf(var + 1e-5f);
    }
    __syncthreads();
    float mean = sh_mean, inv = sh_inv;
    float4 sv = *(const float4*)(s + base);
    float4 biv = *(const float4*)(bias + base);
    float4 ov;
    ov.x = (v[0] - mean) * inv * sv.x + biv.x;
    ov.y = (v[1] - mean) * inv * sv.y + biv.y;
    ov.z = (v[2] - mean) * inv * sv.z + biv.z;
    ov.w = (v[3] - mean) * inv * sv.w + biv.w;
    *(float4*)(out + off) = ov;
}

// ---------------- launch ----------------
extern "C" void kernel_launch(void* const* d_in, const int* in_sizes, int n_in,
                              void* d_out, int out_size) {
    const float* src     = (const float*)d_in[0];
    const unsigned char* mask = (const unsigned char*)d_in[1];
    const float* Wg_attn = (const float*)d_in[2];
    const float* Wqkv    = (const float*)d_in[3];
    const float* bqkv    = (const float*)d_in[4];
    const float* Wo      = (const float*)d_in[5];
    const float* bo      = (const float*)d_in[6];
    const float* Wg_ffn  = (const float*)d_in[7];
    const float* W1      = (const float*)d_in[8];
    const float* b1      = (const float*)d_in[9];
    const float* W2      = (const float*)d_in[10];
    const float* b2      = (const float*)d_in[11];
    const float* ln1_s   = (const float*)d_in[12];
    const float* ln1_b   = (const float*)d_in[13];
    const float* ln2_s   = (const float*)d_in[14];
    const float* ln2_b   = (const float*)d_in[15];
    float* out = (float*)d_out;

    float *qkv, *ctx, *x, *tmp, *hbuf, *gw0, *gw1;
    int *idx0, *idx1, *perm0, *perm1, *te0, *te1;
    cudaGetSymbolAddress((void**)&qkv,  g_qkv);
    cudaGetSymbolAddress((void**)&ctx,  g_ctx);
    cudaGetSymbolAddress((void**)&x,    g_x);
    cudaGetSymbolAddress((void**)&tmp,  g_tmp);
    cudaGetSymbolAddress((void**)&hbuf, g_h);
    cudaGetSymbolAddress((void**)&gw0,  g_gw0);
    cudaGetSymbolAddress((void**)&gw1,  g_gw1);
    cudaGetSymbolAddress((void**)&idx0, g_idx0);
    cudaGetSymbolAddress((void**)&idx1, g_idx1);
    cudaGetSymbolAddress((void**)&perm0, g_perm0);
    cudaGetSymbolAddress((void**)&perm1, g_perm1);
    cudaGetSymbolAddress((void**)&te0,  g_te0);
    cudaGetSymbolAddress((void**)&te1,  g_te1);

    int att_smem = ATT4_SMEM_WORDS * (int)sizeof(uint32_t);
    cudaFuncSetAttribute(attn_mma, cudaFuncAttributeMaxDynamicSharedMemorySize, att_smem);

    // 1. attention gate + grouping
    gate_kernel<<<TKN, 256>>>(src, Wg_attn, idx0, gw0);
    scatter_kernel<<<1, 256>>>(idx0, perm0, te0);
    // 2. QKV projection (bf16 mma, BK=32)
    moe_gemm_mma<<<dim3(3 * DM / 128, MAXTILES, 1), 256>>>(
        src, Wqkv, bqkv, gw0, perm0, te0, qkv, DM, 3 * DM, 0, DM);
    // 3. attention (BQ=128, bf16)
    attn_mma<<<dim3(1024 / 128, 2 * NH), 256, att_smem>>>(qkv, mask, ctx);
    // 4. output projection, split-K x4
    moe_gemm_mma<<<dim3(DM / 128, MAXTILES, 4), 256>>>(
        ctx, Wo, bo, gw0, perm0, te0, tmp, DM, DM, 0, DM / 4);
    // 5. x = LN1(src + 4 partials)
    ln_kernel<<<TKN, 256>>>(src, tmp, 4, ln1_s, ln1_b, x);
    // 6. ffn gate + grouping
    gate_kernel<<<TKN, 256>>>(x, Wg_ffn, idx1, gw1);
    scatter_kernel<<<1, 256>>>(idx1, perm1, te1);
    // 7. h = gelu(gated W1)
    moe_gemm_mma<<<dim3(FFD / 128, MAXTILES, 1), 256>>>(
        x, W1, b1, gw1, perm1, te1, hbuf, DM, FFD, 1, DM);
    // 8. ffn = gated W2, split-K x8
    moe_gemm_mma<<<dim3(DM / 128, MAXTILES, 8), 256>>>(
        hbuf, W2, b2, gw1, perm1, te1, tmp, FFD, DM, 0, FFD / 8);
    // 9. out = LN2(x + 8 partials)
    ln_kernel<<<TKN, 256>>>(x, tmp, 8, ln2_s, ln2_b, out);
}